// round 11
// baseline (speedup 1.0000x reference)
#include <cuda_runtime.h>
#include <cuda_bf16.h>
#include <cstdint>

#define EDIM 1024
#define BDIM 1024
#define G4   4096
#define MAXT 16
#define OUTD 34

#define BM 128
#define BN 128
#define BK 32
#define NCK (EDIM / BK)        // 32 k-chunks
#define NTHREADS 256

#define STAGEB 32768           // Ahi8K + Alo8K + Bhi8K + Blo8K
#define AHI 0
#define ALO 8192
#define BHI 16384
#define BLO 24576
#define SMEM_LSTM (1024 + 2 * STAGEB)   // bias + 2 stages = 66560 (2 CTAs/SM)

#define HSZ (BDIM * EDIM)

// ----------------- device scratch -----------------
__device__ __nv_bfloat16 g_Ws_hi[G4 * EDIM];
__device__ __nv_bfloat16 g_Ws_lo[G4 * EDIM];
__device__ __nv_bfloat16 g_Wh_hi[G4 * EDIM];
__device__ __nv_bfloat16 g_Wh_lo[G4 * EDIM];
__device__ float         g_bsum_p[G4];
// ping-pong h buffers: step t reads parity t&1, writes parity (t+1)&1.
__device__ __nv_bfloat16 g_hhi[2 * HSZ];
__device__ __nv_bfloat16 g_hlo[2 * HSZ];
__device__ float         g_c[HSZ];
__device__ float         g_hseq[MAXT * HSZ];

// ----------------- helpers -----------------
__device__ __forceinline__ uint32_t smem_u32(const void* p) {
    uint32_t a;
    asm("{ .reg .u64 t; cvta.to.shared.u64 t, %1; cvt.u32.u64 %0, t; }" : "=r"(a) : "l"(p));
    return a;
}
__device__ __forceinline__ void cpa16(uint32_t dst, const void* src) {
    asm volatile("cp.async.cg.shared.global [%0], [%1], 16;" :: "r"(dst), "l"(src));
}
__device__ __forceinline__ void cpa_commit() {
    asm volatile("cp.async.commit_group;" ::: "memory");
}
__device__ __forceinline__ void ldsm4(uint32_t* r, uint32_t a) {
    asm volatile("ldmatrix.sync.aligned.m8n8.x4.shared.b16 {%0,%1,%2,%3}, [%4];"
                 : "=r"(r[0]), "=r"(r[1]), "=r"(r[2]), "=r"(r[3]) : "r"(a));
}
__device__ __forceinline__ void mma16816(float* d,
                                         const uint32_t* a,
                                         uint32_t b0, uint32_t b1) {
    asm volatile("mma.sync.aligned.m16n8k16.row.col.f32.bf16.bf16.f32 "
                 "{%0,%1,%2,%3}, {%4,%5,%6,%7}, {%8,%9}, {%0,%1,%2,%3};"
                 : "+f"(d[0]), "+f"(d[1]), "+f"(d[2]), "+f"(d[3])
                 : "r"(a[0]), "r"(a[1]), "r"(a[2]), "r"(a[3]), "r"(b0), "r"(b1));
}
__device__ __forceinline__ float fsig(float x) {
    float t = __expf(-x);
    return __fdividef(1.f, 1.f + t);
}
__device__ __forceinline__ float ftanh_(float x) {
    float t = __expf(-2.f * x);
    return __fdividef(1.f - t, 1.f + t);
}
// truncation split of 4 floats into packed bf16 hi/lo pairs (2 u32 each)
__device__ __forceinline__ void tsplit4(float4 v, uint2& hi, uint2& lo) {
    uint32_t ux = __float_as_uint(v.x), uy = __float_as_uint(v.y);
    uint32_t uz = __float_as_uint(v.z), uw = __float_as_uint(v.w);
    hi.x = __byte_perm(ux, uy, 0x7632);
    hi.y = __byte_perm(uz, uw, 0x7632);
    float lx = v.x - __uint_as_float(ux & 0xFFFF0000u);
    float ly = v.y - __uint_as_float(uy & 0xFFFF0000u);
    float lz = v.z - __uint_as_float(uz & 0xFFFF0000u);
    float lw = v.w - __uint_as_float(uw & 0xFFFF0000u);
    lo.x = __byte_perm(__float_as_uint(lx), __float_as_uint(ly), 0x7632);
    lo.y = __byte_perm(__float_as_uint(lz), __float_as_uint(lw), 0x7632);
}

// permutation: original W row r = g*1024 + e  ->  rp = (e>>5)*128 + g*32 + (e&31)
// so N-block nb (128 rows) holds e in [nb*32, nb*32+32) for all 4 gates,
// gate g at local rows [g*32, g*32+32).

// ----------------- prep kernels -----------------
__global__ void prep_w(const float* __restrict__ Wih, const float* __restrict__ Whh) {
    int id = blockIdx.x * 256 + threadIdx.x;
    int r = id >> 8;
    int q = id & 255;
    float4 a = reinterpret_cast<const float4*>(Wih)[(size_t)r * 256 + q];
    float4 b = reinterpret_cast<const float4*>(Whh)[(size_t)r * 256 + q];
    int g = r >> 10, e = r & 1023;
    int rp = ((e >> 5) << 7) + (g << 5) + (e & 31);
    size_t o = (size_t)rp * 256 + q;   // 8-byte units (4 bf16)

    uint2 hh, hl, sh, sl;
    tsplit4(b, hh, hl);
    float4 s = make_float4(a.x + b.x, a.y + b.y, a.z + b.z, a.w + b.w);
    tsplit4(s, sh, sl);

    reinterpret_cast<uint2*>(g_Wh_hi)[o] = hh;
    reinterpret_cast<uint2*>(g_Wh_lo)[o] = hl;
    reinterpret_cast<uint2*>(g_Ws_hi)[o] = sh;
    reinterpret_cast<uint2*>(g_Ws_lo)[o] = sl;
}

__global__ void prep_state(const float* __restrict__ h0, const float* __restrict__ c0,
                           const float* __restrict__ bih, const float* __restrict__ bhh) {
    int id = blockIdx.x * 256 + threadIdx.x;
    float4 hv = reinterpret_cast<const float4*>(h0)[id];
    uint2 hh, hl;
    tsplit4(hv, hh, hl);
    reinterpret_cast<uint2*>(g_hhi)[id] = hh;   // parity-0 buffer
    reinterpret_cast<uint2*>(g_hlo)[id] = hl;
    reinterpret_cast<float4*>(g_c)[id] = reinterpret_cast<const float4*>(c0)[id];
    if (id < G4) {
        int g = id >> 10, e = id & 1023;
        int rp = ((e >> 5) << 7) + (g << 5) + (e & 31);
        g_bsum_p[rp] = bih[id] + bhh[id];
    }
}

// ----------------- fused GEMM (mma.sync bf16 3-term) + LSTM update -----------------
__global__ __launch_bounds__(NTHREADS, 2)
void lstm_step(int use_sum, int t) {
    extern __shared__ char smem[];
    float* bias_sm = reinterpret_cast<float*>(smem);
    const uint32_t sbase = smem_u32(smem) + 1024;
    const int tid = threadIdx.x;
    const int lane = tid & 31;
    const int w = tid >> 5;        // 0..7
    const int wm = w & 3;          // m-group (32 rows)
    const int we = w >> 2;         // e-group (16 e-cols): 0..1
    const int nb = blockIdx.x;     // 0..31
    const int mb = blockIdx.y;     // 0..7
    const int m0 = mb * BM, n0 = nb * BN;

    // ping-pong: read parity t&1, write parity (t+1)&1
    const __nv_bfloat16* __restrict__ hin_hi = g_hhi + (size_t)(t & 1) * HSZ;
    const __nv_bfloat16* __restrict__ hin_lo = g_hlo + (size_t)(t & 1) * HSZ;
    __nv_bfloat16* __restrict__ hout_hi = g_hhi + (size_t)((t + 1) & 1) * HSZ;
    __nv_bfloat16* __restrict__ hout_lo = g_hlo + (size_t)((t + 1) & 1) * HSZ;

    const __nv_bfloat16* __restrict__ Bh = use_sum ? g_Ws_hi : g_Wh_hi;
    const __nv_bfloat16* __restrict__ Bl = use_sum ? g_Ws_lo : g_Wh_lo;

    if (tid < BN) bias_sm[tid] = g_bsum_p[n0 + tid];

    // ---- loaders: 8 cp.async per thread per stage (256 threads, 32KB) ----
    const int lrow = tid >> 2;     // 0..63
    const int lq = tid & 3;        // quad within 64B row

#define LOAD_STAGE(s, kc)                                                          \
    {                                                                              \
        uint32_t sb = sbase + (s) * STAGEB;                                        \
        size_t gc = (size_t)(kc) * 32 + lq * 8;                                    \
        _Pragma("unroll")                                                          \
        for (int i = 0; i < 2; ++i) {                                              \
            int row = lrow + i * 64;                                               \
            uint32_t sf = (uint32_t)row * 64 + (((lq ^ ((row >> 1) & 3)) << 4));   \
            cpa16(sb + AHI + sf, hin_hi + (size_t)(m0 + row) * EDIM + gc);         \
            cpa16(sb + ALO + sf, hin_lo + (size_t)(m0 + row) * EDIM + gc);         \
            cpa16(sb + BHI + sf, Bh + (size_t)(n0 + row) * EDIM + gc);             \
            cpa16(sb + BLO + sf, Bl + (size_t)(n0 + row) * EDIM + gc);             \
        }                                                                          \
        cpa_commit();                                                              \
    }

    // acc[mt][gate][sub][4] : m-tile mt (16 rows), gate, n8 sub-tile
    float acc[2][4][2][4];
#pragma unroll
    for (int i = 0; i < 2; ++i)
#pragma unroll
        for (int j = 0; j < 4; ++j)
#pragma unroll
            for (int s = 0; s < 2; ++s)
#pragma unroll
                for (int k = 0; k < 4; ++k) acc[i][j][s][k] = 0.f;

    // ldmatrix lane geometry
    const int arl = (lane & 7) + ((lane >> 3) & 1) * 8;   // A row within m16
    const int adq = lane >> 4;                            // A k-quad offset (0/1)
    const int bn = (lane & 7) + ((lane >> 4) << 3);       // B n within n16
    const int bdq = (lane >> 3) & 1;                      // B k-quad offset

    // prologue: chunk 0 only (single group in flight)
    LOAD_STAGE(0, 0)

    for (int kc = 0; kc < NCK; ++kc) {
        asm volatile("cp.async.wait_group 0;" ::: "memory");  // chunk kc resident
        __syncthreads();          // visible; stage (kc+1)&1 free (all done kc-1)
        if (kc + 1 < NCK) {
            LOAD_STAGE((kc + 1) & 1, kc + 1)                  // overlaps compute
        }

        uint32_t sb = sbase + (kc & 1) * STAGEB;
#pragma unroll
        for (int k16 = 0; k16 < 2; ++k16) {
            int qa = k16 * 2 + adq;
            int qb = k16 * 2 + bdq;
            uint32_t aoffs[2], boffs[4];
#pragma unroll
            for (int mt = 0; mt < 2; ++mt) {
                int ar = wm * 32 + mt * 16 + arl;
                aoffs[mt] = (uint32_t)ar * 64 + ((qa ^ ((ar >> 1) & 3)) << 4);
            }
#pragma unroll
            for (int g = 0; g < 4; ++g) {
                int br = g * 32 + we * 16 + bn;
                boffs[g] = (uint32_t)br * 64 + ((qb ^ ((br >> 1) & 3)) << 4);
            }
            uint32_t ah[2][4], bf[4][4];
#pragma unroll
            for (int mt = 0; mt < 2; ++mt) ldsm4(ah[mt], sb + AHI + aoffs[mt]);
#pragma unroll
            for (int g = 0; g < 4; ++g) ldsm4(bf[g], sb + BHI + boffs[g]);
            // pass 1: hi*hi
#pragma unroll
            for (int mt = 0; mt < 2; ++mt)
#pragma unroll
                for (int g = 0; g < 4; ++g) {
                    mma16816(acc[mt][g][0], ah[mt], bf[g][0], bf[g][1]);
                    mma16816(acc[mt][g][1], ah[mt], bf[g][2], bf[g][3]);
                }
            // pass 2: lo*hi (al live only here)
            {
                uint32_t al[2][4];
#pragma unroll
                for (int mt = 0; mt < 2; ++mt) ldsm4(al[mt], sb + ALO + aoffs[mt]);
#pragma unroll
                for (int mt = 0; mt < 2; ++mt)
#pragma unroll
                    for (int g = 0; g < 4; ++g) {
                        mma16816(acc[mt][g][0], al[mt], bf[g][0], bf[g][1]);
                        mma16816(acc[mt][g][1], al[mt], bf[g][2], bf[g][3]);
                    }
            }
            // pass 3: hi*lo (reuse bf registers for BLO fragments)
#pragma unroll
            for (int g = 0; g < 4; ++g) ldsm4(bf[g], sb + BLO + boffs[g]);
#pragma unroll
            for (int mt = 0; mt < 2; ++mt)
#pragma unroll
                for (int g = 0; g < 4; ++g) {
                    mma16816(acc[mt][g][0], ah[mt], bf[g][0], bf[g][1]);
                    mma16816(acc[mt][g][1], ah[mt], bf[g][2], bf[g][3]);
                }
        }
    }

    // ---- fused epilogue: per-thread register LSTM update ----
    const int mbase = m0 + wm * 32 + (lane >> 2);
    const int cp2 = (lane & 3) * 2;
    float* hseq = g_hseq + (size_t)t * HSZ;
#pragma unroll
    for (int mt = 0; mt < 2; ++mt) {
#pragma unroll
        for (int rr = 0; rr < 2; ++rr) {
            int m = mbase + mt * 16 + rr * 8;
#pragma unroll
            for (int sub = 0; sub < 2; ++sub) {
                int el = we * 16 + sub * 8 + cp2;
                float xi0 = acc[mt][0][sub][rr*2+0] + bias_sm[el];
                float xi1 = acc[mt][0][sub][rr*2+1] + bias_sm[el + 1];
                float xf0 = acc[mt][1][sub][rr*2+0] + bias_sm[32 + el];
                float xf1 = acc[mt][1][sub][rr*2+1] + bias_sm[32 + el + 1];
                float xg0 = acc[mt][2][sub][rr*2+0] + bias_sm[64 + el];
                float xg1 = acc[mt][2][sub][rr*2+1] + bias_sm[64 + el + 1];
                float xo0 = acc[mt][3][sub][rr*2+0] + bias_sm[96 + el];
                float xo1 = acc[mt][3][sub][rr*2+1] + bias_sm[96 + el + 1];
                size_t off = (size_t)m * EDIM + nb * 32 + el;
                float2 cold = *reinterpret_cast<const float2*>(g_c + off);
                float cn0 = fsig(xf0) * cold.x + fsig(xi0) * ftanh_(xg0);
                float cn1 = fsig(xf1) * cold.y + fsig(xi1) * ftanh_(xg1);
                float hn0 = fsig(xo0) * ftanh_(cn0);
                float hn1 = fsig(xo1) * ftanh_(cn1);
                *reinterpret_cast<float2*>(g_c + off) = make_float2(cn0, cn1);
                *reinterpret_cast<float2*>(hseq + off) = make_float2(hn0, hn1);
                // truncation split + PRMT pack
                uint32_t u0 = __float_as_uint(hn0), u1 = __float_as_uint(hn1);
                uint32_t hip = __byte_perm(u0, u1, 0x7632);
                float l0 = hn0 - __uint_as_float(u0 & 0xFFFF0000u);
                float l1 = hn1 - __uint_as_float(u1 & 0xFFFF0000u);
                uint32_t lop = __byte_perm(__float_as_uint(l0), __float_as_uint(l1), 0x7632);
                *reinterpret_cast<uint32_t*>(reinterpret_cast<unsigned short*>(hout_hi) + off) = hip;
                *reinterpret_cast<uint32_t*>(reinterpret_cast<unsigned short*>(hout_lo) + off) = lop;
            }
        }
    }
}

// ----------------- output projection -----------------
#define OPR 16
#define OPSTRIDE 1040
__global__ void out_proj(const float* __restrict__ Wo, const float* __restrict__ bo,
                         float* __restrict__ out, int T) {
    extern __shared__ float hs[];
    int t = blockIdx.y;
    int b0 = blockIdx.x * OPR;
    int tid = threadIdx.y * 17 + threadIdx.x;
    const float4* src = reinterpret_cast<const float4*>(g_hseq + ((size_t)t * BDIM + b0) * EDIM);
    for (int i = tid; i < OPR * 256; i += 136) {
        int r = i >> 8, c = i & 255;
        reinterpret_cast<float4*>(hs + r * OPSTRIDE)[c] = src[(size_t)r * 256 + c];
    }
    __syncthreads();
    int o0 = threadIdx.x * 2, o1 = o0 + 1;
    int r0 = threadIdx.y * 2, r1 = r0 + 1;
    const float4* w0 = reinterpret_cast<const float4*>(Wo + (size_t)o0 * EDIM);
    const float4* w1 = reinterpret_cast<const float4*>(Wo + (size_t)o1 * EDIM);
    const float4* h0 = reinterpret_cast<const float4*>(hs + r0 * OPSTRIDE);
    const float4* h1 = reinterpret_cast<const float4*>(hs + r1 * OPSTRIDE);
    float s00 = 0.f, s01 = 0.f, s10 = 0.f, s11 = 0.f;
#pragma unroll 4
    for (int k = 0; k < 256; ++k) {
        float4 a = h0[k], b = h1[k], x = w0[k], y = w1[k];
        s00 += a.x * x.x + a.y * x.y + a.z * x.z + a.w * x.w;
        s01 += a.x * y.x + a.y * y.y + a.z * y.z + a.w * y.w;
        s10 += b.x * x.x + b.y * x.y + b.z * x.z + b.w * x.w;
        s11 += b.x * y.x + b.y * y.y + b.z * y.z + b.w * y.w;
    }
    float bb0 = bo[o0], bb1 = bo[o1];
    size_t ob = ((size_t)(b0 + r0) * T + t) * OUTD;
    out[ob + o0] = s00 + bb0;
    out[ob + o1] = s01 + bb1;
    ob = ((size_t)(b0 + r1) * T + t) * OUTD;
    out[ob + o0] = s10 + bb0;
    out[ob + o1] = s11 + bb1;
}

// ----------------- launch -----------------
extern "C" void kernel_launch(void* const* d_in, const int* in_sizes, int n_in,
                              void* d_out, int out_size) {
    const float* h     = (const float*)d_in[0];
    const float* c     = (const float*)d_in[1];
    const float* W_ih  = (const float*)d_in[2];
    const float* W_hh  = (const float*)d_in[3];
    const float* b_ih  = (const float*)d_in[4];
    const float* b_hh  = (const float*)d_in[5];
    const float* W_out = (const float*)d_in[6];
    const float* b_out = (const float*)d_in[7];
    float* out = (float*)d_out;

    int T = out_size / (BDIM * OUTD);
    if (T < 1) T = 1;
    if (T > MAXT) T = MAXT;

    cudaFuncSetAttribute(lstm_step, cudaFuncAttributeMaxDynamicSharedMemorySize, SMEM_LSTM);
    cudaFuncSetAttribute(out_proj, cudaFuncAttributeMaxDynamicSharedMemorySize,
                         OPR * OPSTRIDE * 4);

    prep_w<<<G4, 256>>>(W_ih, W_hh);
    prep_state<<<(BDIM * EDIM / 4) / 256, 256>>>(h, c, b_ih, b_hh);

    dim3 grid(G4 / BN, BDIM / BM);   // (32, 8) = 256 CTAs, 2 per SM
    for (int t = 0; t < T; ++t)
        lstm_step<<<grid, NTHREADS, SMEM_LSTM>>>(t > 0 ? 1 : 0, t);

    dim3 opgrid(BDIM / OPR, T);
    dim3 opblk(17, 8);
    out_proj<<<opgrid, opblk, OPR * OPSTRIDE * 4>>>(W_out, b_out, out, T);
}

// round 12
// speedup vs baseline: 1.0639x; 1.0639x over previous
#include <cuda_runtime.h>
#include <cuda_bf16.h>
#include <cstdint>

#define EDIM 1024
#define BDIM 1024
#define G4   4096
#define MAXT 16
#define OUTD 34

#define BM 128
#define BN 256
#define BK 64
#define NCK (EDIM / BK)        // 16 k-chunks
#define NTHREADS 512
#define NCTAS 128

#define STAGEB 98304           // Ahi16K + Alo16K + Bhi32K + Blo32K
#define AHI 0
#define ALO 16384
#define BHI 32768
#define BLO 65536
#define SMEM_LSTM (1024 + 2 * STAGEB)   // bias + 2 stages = 197632

#define HSZ (BDIM * EDIM)

// ----------------- device scratch -----------------
__device__ __nv_bfloat16 g_Ws_hi[G4 * EDIM];
__device__ __nv_bfloat16 g_Ws_lo[G4 * EDIM];
__device__ __nv_bfloat16 g_Wh_hi[G4 * EDIM];
__device__ __nv_bfloat16 g_Wh_lo[G4 * EDIM];
__device__ float         g_bsum_p[G4];
// ping-pong h buffers: step t reads parity t&1, writes parity (t+1)&1.
__device__ __nv_bfloat16 g_hhi[2 * HSZ];
__device__ __nv_bfloat16 g_hlo[2 * HSZ];
__device__ float         g_c[HSZ];
__device__ float         g_hseq[MAXT * HSZ];
__device__ unsigned int  g_bar;            // grid barrier counter (reset each launch)

// ----------------- helpers -----------------
__device__ __forceinline__ uint32_t smem_u32(const void* p) {
    uint32_t a;
    asm("{ .reg .u64 t; cvta.to.shared.u64 t, %1; cvt.u32.u64 %0, t; }" : "=r"(a) : "l"(p));
    return a;
}
__device__ __forceinline__ void cpa16(uint32_t dst, const void* src) {
    asm volatile("cp.async.cg.shared.global [%0], [%1], 16;" :: "r"(dst), "l"(src));
}
__device__ __forceinline__ void cpa_commit() {
    asm volatile("cp.async.commit_group;" ::: "memory");
}
__device__ __forceinline__ void ldsm4(uint32_t* r, uint32_t a) {
    asm volatile("ldmatrix.sync.aligned.m8n8.x4.shared.b16 {%0,%1,%2,%3}, [%4];"
                 : "=r"(r[0]), "=r"(r[1]), "=r"(r[2]), "=r"(r[3]) : "r"(a));
}
__device__ __forceinline__ void mma16816(float* d,
                                         const uint32_t* a,
                                         uint32_t b0, uint32_t b1) {
    asm volatile("mma.sync.aligned.m16n8k16.row.col.f32.bf16.bf16.f32 "
                 "{%0,%1,%2,%3}, {%4,%5,%6,%7}, {%8,%9}, {%0,%1,%2,%3};"
                 : "+f"(d[0]), "+f"(d[1]), "+f"(d[2]), "+f"(d[3])
                 : "r"(a[0]), "r"(a[1]), "r"(a[2]), "r"(a[3]), "r"(b0), "r"(b1));
}
__device__ __forceinline__ float fsig(float x) {
    float t = __expf(-x);
    return __fdividef(1.f, 1.f + t);
}
__device__ __forceinline__ float ftanh_(float x) {
    float t = __expf(-2.f * x);
    return __fdividef(1.f - t, 1.f + t);
}
__device__ __forceinline__ void bsplit(float v, unsigned short& h, unsigned short& l) {
    __nv_bfloat16 hb = __float2bfloat16(v);
    float r = v - __bfloat162float(hb);
    __nv_bfloat16 lb = __float2bfloat16(r);
    h = __bfloat16_as_ushort(hb);
    l = __bfloat16_as_ushort(lb);
}

// permutation: original W row r = g*1024 + e  ->  rp = (e>>6)*256 + g*64 + (e&63)

// ----------------- prep kernels -----------------
__global__ void prep_w(const float* __restrict__ Wih, const float* __restrict__ Whh) {
    int id = blockIdx.x * 256 + threadIdx.x;
    int r = id >> 8;
    int q = id & 255;
    float4 a = reinterpret_cast<const float4*>(Wih)[(size_t)r * 256 + q];
    float4 b = reinterpret_cast<const float4*>(Whh)[(size_t)r * 256 + q];
    int g = r >> 10, e = r & 1023;
    int rp = ((e >> 6) << 8) + (g << 6) + (e & 63);
    size_t o = (size_t)rp * 256 + q;

    ushort4 hh, hl, sh, sl;
    bsplit(b.x, hh.x, hl.x); bsplit(b.y, hh.y, hl.y);
    bsplit(b.z, hh.z, hl.z); bsplit(b.w, hh.w, hl.w);
    float4 s = make_float4(a.x + b.x, a.y + b.y, a.z + b.z, a.w + b.w);
    bsplit(s.x, sh.x, sl.x); bsplit(s.y, sh.y, sl.y);
    bsplit(s.z, sh.z, sl.z); bsplit(s.w, sh.w, sl.w);

    reinterpret_cast<ushort4*>(g_Wh_hi)[o] = hh;
    reinterpret_cast<ushort4*>(g_Wh_lo)[o] = hl;
    reinterpret_cast<ushort4*>(g_Ws_hi)[o] = sh;
    reinterpret_cast<ushort4*>(g_Ws_lo)[o] = sl;
}

__global__ void prep_state(const float* __restrict__ h0, const float* __restrict__ c0,
                           const float* __restrict__ bih, const float* __restrict__ bhh) {
    int id = blockIdx.x * 256 + threadIdx.x;
    if (id == 0) g_bar = 0u;                 // reset grid barrier each launch
    float4 hv = reinterpret_cast<const float4*>(h0)[id];
    ushort4 hh, hl;
    bsplit(hv.x, hh.x, hl.x); bsplit(hv.y, hh.y, hl.y);
    bsplit(hv.z, hh.z, hl.z); bsplit(hv.w, hh.w, hl.w);
    reinterpret_cast<ushort4*>(g_hhi)[id] = hh;
    reinterpret_cast<ushort4*>(g_hlo)[id] = hl;
    reinterpret_cast<float4*>(g_c)[id] = reinterpret_cast<const float4*>(c0)[id];
    if (id < G4) {
        int g = id >> 10, e = id & 1023;
        int rp = ((e >> 6) << 8) + (g << 6) + (e & 63);
        g_bsum_p[rp] = bih[id] + bhh[id];
    }
}

// ----------------- persistent fused GEMM + LSTM (all T steps, grid barrier) ---
__global__ __launch_bounds__(NTHREADS, 1)
void lstm_persist(int T) {
    extern __shared__ char smem[];
    float* bias_sm = reinterpret_cast<float*>(smem);
    const uint32_t sbase = smem_u32(smem) + 1024;
    const int tid = threadIdx.x;
    const int lane = tid & 31;
    const int w = tid >> 5;        // 0..15
    const int wm = w & 3;          // m-group (32 rows)
    const int we = w >> 2;         // e-group (16 e-cols)
    const int nb = blockIdx.x;     // 0..15
    const int mb = blockIdx.y;     // 0..7
    const int m0 = mb * BM, n0 = nb * BN;

    if (tid < BN) bias_sm[tid] = g_bsum_p[n0 + tid];
    __syncthreads();

    const int lrow = tid >> 3;     // 0..63
    const int lq = tid & 7;

    // ldmatrix lane geometry
    const int arl = (lane & 7) + ((lane >> 3) & 1) * 8;
    const int adq = lane >> 4;
    const int bn = (lane & 7) + ((lane >> 4) << 3);
    const int bdq = (lane >> 3) & 1;

    const int mbase = m0 + wm * 32 + (lane >> 2);
    const int cp2 = (lane & 3) * 2;

#define LOAD_STAGE(s, kc)                                                          \
    {                                                                              \
        uint32_t sb = sbase + (s) * STAGEB;                                        \
        size_t gc = (size_t)(kc) * 64 + lq * 8;                                    \
        _Pragma("unroll")                                                          \
        for (int i = 0; i < 2; ++i) {                                              \
            int row = lrow + i * 64;                                               \
            uint32_t sf = (uint32_t)row * 128 + (((lq ^ (row & 7)) << 4));         \
            cpa16(sb + AHI + sf, hin_hi + (size_t)(m0 + row) * EDIM + gc);         \
            cpa16(sb + ALO + sf, hin_lo + (size_t)(m0 + row) * EDIM + gc);         \
        }                                                                          \
        _Pragma("unroll")                                                          \
        for (int i = 0; i < 4; ++i) {                                              \
            int row = lrow + i * 64;                                               \
            uint32_t sf = (uint32_t)row * 128 + (((lq ^ (row & 7)) << 4));         \
            cpa16(sb + BHI + sf, Bh + (size_t)(n0 + row) * EDIM + gc);             \
            cpa16(sb + BLO + sf, Bl + (size_t)(n0 + row) * EDIM + gc);             \
        }                                                                          \
        cpa_commit();                                                              \
    }

    for (int t = 0; t < T; ++t) {
        const __nv_bfloat16* hin_hi = g_hhi + (size_t)(t & 1) * HSZ;
        const __nv_bfloat16* hin_lo = g_hlo + (size_t)(t & 1) * HSZ;
        __nv_bfloat16* hout_hi = g_hhi + (size_t)((t + 1) & 1) * HSZ;
        __nv_bfloat16* hout_lo = g_hlo + (size_t)((t + 1) & 1) * HSZ;
        const __nv_bfloat16* Bh = t ? g_Ws_hi : g_Wh_hi;
        const __nv_bfloat16* Bl = t ? g_Ws_lo : g_Wh_lo;

        float acc[2][4][2][4];
#pragma unroll
        for (int i = 0; i < 2; ++i)
#pragma unroll
            for (int j = 0; j < 4; ++j)
#pragma unroll
                for (int s = 0; s < 2; ++s)
#pragma unroll
                    for (int k = 0; k < 4; ++k) acc[i][j][s][k] = 0.f;

        LOAD_STAGE(0, 0)

        for (int kc = 0; kc < NCK; ++kc) {
            asm volatile("cp.async.wait_group 0;" ::: "memory");
            __syncthreads();
            if (kc + 1 < NCK) {
                LOAD_STAGE((kc + 1) & 1, kc + 1)
            }

            uint32_t sb = sbase + (kc & 1) * STAGEB;
#pragma unroll
            for (int k16 = 0; k16 < 4; ++k16) {
                int qa = k16 * 2 + adq;
                int qb = k16 * 2 + bdq;
                uint32_t aoffs[2], boffs[4];
#pragma unroll
                for (int mt = 0; mt < 2; ++mt) {
                    int ar = wm * 32 + mt * 16 + arl;
                    aoffs[mt] = (uint32_t)ar * 128 + ((qa ^ (ar & 7)) << 4);
                }
#pragma unroll
                for (int g = 0; g < 4; ++g) {
                    int br = g * 64 + we * 16 + bn;
                    boffs[g] = (uint32_t)br * 128 + ((qb ^ (br & 7)) << 4);
                }
                uint32_t ah[2][4], bf[4][4];
#pragma unroll
                for (int mt = 0; mt < 2; ++mt) ldsm4(ah[mt], sb + AHI + aoffs[mt]);
#pragma unroll
                for (int g = 0; g < 4; ++g) ldsm4(bf[g], sb + BHI + boffs[g]);
                // pass 1: hi*hi
#pragma unroll
                for (int mt = 0; mt < 2; ++mt)
#pragma unroll
                    for (int g = 0; g < 4; ++g) {
                        mma16816(acc[mt][g][0], ah[mt], bf[g][0], bf[g][1]);
                        mma16816(acc[mt][g][1], ah[mt], bf[g][2], bf[g][3]);
                    }
                // pass 2: lo*hi
                {
                    uint32_t al[2][4];
#pragma unroll
                    for (int mt = 0; mt < 2; ++mt) ldsm4(al[mt], sb + ALO + aoffs[mt]);
#pragma unroll
                    for (int mt = 0; mt < 2; ++mt)
#pragma unroll
                        for (int g = 0; g < 4; ++g) {
                            mma16816(acc[mt][g][0], al[mt], bf[g][0], bf[g][1]);
                            mma16816(acc[mt][g][1], al[mt], bf[g][2], bf[g][3]);
                        }
                }
                // pass 3: hi*lo (reuse bf regs)
#pragma unroll
                for (int g = 0; g < 4; ++g) ldsm4(bf[g], sb + BLO + boffs[g]);
#pragma unroll
                for (int mt = 0; mt < 2; ++mt)
#pragma unroll
                    for (int g = 0; g < 4; ++g) {
                        mma16816(acc[mt][g][0], ah[mt], bf[g][0], bf[g][1]);
                        mma16816(acc[mt][g][1], ah[mt], bf[g][2], bf[g][3]);
                    }
            }
        }

        // ---- fused epilogue ----
        float* hseq = g_hseq + (size_t)t * HSZ;
#pragma unroll
        for (int mt = 0; mt < 2; ++mt) {
#pragma unroll
            for (int rr = 0; rr < 2; ++rr) {
                int m = mbase + mt * 16 + rr * 8;
#pragma unroll
                for (int sub = 0; sub < 2; ++sub) {
                    int el = we * 16 + sub * 8 + cp2;
                    float xi0 = acc[mt][0][sub][rr*2+0] + bias_sm[el];
                    float xi1 = acc[mt][0][sub][rr*2+1] + bias_sm[el + 1];
                    float xf0 = acc[mt][1][sub][rr*2+0] + bias_sm[64 + el];
                    float xf1 = acc[mt][1][sub][rr*2+1] + bias_sm[64 + el + 1];
                    float xg0 = acc[mt][2][sub][rr*2+0] + bias_sm[128 + el];
                    float xg1 = acc[mt][2][sub][rr*2+1] + bias_sm[128 + el + 1];
                    float xo0 = acc[mt][3][sub][rr*2+0] + bias_sm[192 + el];
                    float xo1 = acc[mt][3][sub][rr*2+1] + bias_sm[192 + el + 1];
                    size_t off = (size_t)m * EDIM + nb * 64 + el;
                    float2 cold = *reinterpret_cast<const float2*>(g_c + off);
                    float cn0 = fsig(xf0) * cold.x + fsig(xi0) * ftanh_(xg0);
                    float cn1 = fsig(xf1) * cold.y + fsig(xi1) * ftanh_(xg1);
                    float hn0 = fsig(xo0) * ftanh_(cn0);
                    float hn1 = fsig(xo1) * ftanh_(cn1);
                    *reinterpret_cast<float2*>(g_c + off) = make_float2(cn0, cn1);
                    *reinterpret_cast<float2*>(hseq + off) = make_float2(hn0, hn1);
                    unsigned short h0, l0, h1, l1;
                    bsplit(hn0, h0, l0);
                    bsplit(hn1, h1, l1);
                    *reinterpret_cast<uint32_t*>(reinterpret_cast<unsigned short*>(hout_hi) + off) =
                        (uint32_t)h0 | ((uint32_t)h1 << 16);
                    *reinterpret_cast<uint32_t*>(reinterpret_cast<unsigned short*>(hout_lo) + off) =
                        (uint32_t)l0 | ((uint32_t)l1 << 16);
                }
            }
        }

        // ---- inter-step grid barrier (all 128 CTAs co-resident) ----
        if (t + 1 < T) {
            __threadfence();
            __syncthreads();
            if (tid == 0) {
                unsigned tgt = (unsigned)(t + 1) * (unsigned)NCTAS;
                atomicAdd(&g_bar, 1u);
                while (atomicAdd(&g_bar, 0u) < tgt) __nanosleep(64);
            }
            __syncthreads();
        }
    }
#undef LOAD_STAGE
}

// ----------------- output projection -----------------
#define OPR 16
#define OPSTRIDE 1040
__global__ void out_proj(const float* __restrict__ Wo, const float* __restrict__ bo,
                         float* __restrict__ out, int T) {
    extern __shared__ float hs[];
    int t = blockIdx.y;
    int b0 = blockIdx.x * OPR;
    int tid = threadIdx.y * 17 + threadIdx.x;
    const float4* src = reinterpret_cast<const float4*>(g_hseq + ((size_t)t * BDIM + b0) * EDIM);
    for (int i = tid; i < OPR * 256; i += 136) {
        int r = i >> 8, c = i & 255;
        reinterpret_cast<float4*>(hs + r * OPSTRIDE)[c] = src[(size_t)r * 256 + c];
    }
    __syncthreads();
    int o0 = threadIdx.x * 2, o1 = o0 + 1;
    int r0 = threadIdx.y * 2, r1 = r0 + 1;
    const float4* w0 = reinterpret_cast<const float4*>(Wo + (size_t)o0 * EDIM);
    const float4* w1 = reinterpret_cast<const float4*>(Wo + (size_t)o1 * EDIM);
    const float4* h0 = reinterpret_cast<const float4*>(hs + r0 * OPSTRIDE);
    const float4* h1 = reinterpret_cast<const float4*>(hs + r1 * OPSTRIDE);
    float s00 = 0.f, s01 = 0.f, s10 = 0.f, s11 = 0.f;
#pragma unroll 4
    for (int k = 0; k < 256; ++k) {
        float4 a = h0[k], b = h1[k], x = w0[k], y = w1[k];
        s00 += a.x * x.x + a.y * x.y + a.z * x.z + a.w * x.w;
        s01 += a.x * y.x + a.y * y.y + a.z * y.z + a.w * y.w;
        s10 += b.x * x.x + b.y * x.y + b.z * x.z + b.w * x.w;
        s11 += b.x * y.x + b.y * y.y + b.z * y.z + b.w * y.w;
    }
    float bb0 = bo[o0], bb1 = bo[o1];
    size_t ob = ((size_t)(b0 + r0) * T + t) * OUTD;
    out[ob + o0] = s00 + bb0;
    out[ob + o1] = s01 + bb1;
    ob = ((size_t)(b0 + r1) * T + t) * OUTD;
    out[ob + o0] = s10 + bb0;
    out[ob + o1] = s11 + bb1;
}

// ----------------- launch -----------------
extern "C" void kernel_launch(void* const* d_in, const int* in_sizes, int n_in,
                              void* d_out, int out_size) {
    const float* h     = (const float*)d_in[0];
    const float* c     = (const float*)d_in[1];
    const float* W_ih  = (const float*)d_in[2];
    const float* W_hh  = (const float*)d_in[3];
    const float* b_ih  = (const float*)d_in[4];
    const float* b_hh  = (const float*)d_in[5];
    const float* W_out = (const float*)d_in[6];
    const float* b_out = (const float*)d_in[7];
    float* out = (float*)d_out;

    int T = out_size / (BDIM * OUTD);
    if (T < 1) T = 1;
    if (T > MAXT) T = MAXT;

    cudaFuncSetAttribute(lstm_persist, cudaFuncAttributeMaxDynamicSharedMemorySize, SMEM_LSTM);
    cudaFuncSetAttribute(out_proj, cudaFuncAttributeMaxDynamicSharedMemorySize,
                         OPR * OPSTRIDE * 4);

    prep_w<<<G4, 256>>>(W_ih, W_hh);
    prep_state<<<(BDIM * EDIM / 4) / 256, 256>>>(h, c, b_ih, b_hh);

    dim3 grid(G4 / BN, BDIM / BM);   // (16, 8) = 128 CTAs = 1 per SM, all resident
    lstm_persist<<<grid, NTHREADS, SMEM_LSTM>>>(T);

    dim3 opgrid(BDIM / OPR, T);
    dim3 opblk(17, 8);
    out_proj<<<opgrid, opblk, OPR * OPSTRIDE * 4>>>(W_out, b_out, out, T);
}

// round 13
// speedup vs baseline: 1.3711x; 1.2888x over previous
#include <cuda_runtime.h>
#include <cuda_bf16.h>
#include <cstdint>

#define EDIM 1024
#define BDIM 1024
#define G4   4096
#define MAXT 16
#define OUTD 34

#define BM 128
#define BN 256
#define BK 64
#define NCK (EDIM / BK)        // 16 k-chunks
#define NTHREADS 512
#define NCTAS 128

#define STAGEB 98304           // Ahi16K + Alo16K + Bhi32K + Blo32K
#define AHI 0
#define ALO 16384
#define BHI 32768
#define BLO 65536
#define SMEM_LSTM (1024 + 2 * STAGEB)   // bias + 2 stages = 197632

#define HSZ (BDIM * EDIM)

// out_proj GEMM tiling
#define ONB 64                 // padded N (34 -> 64)
#define OSTAGE 49152           // Ahi16K+Alo16K+Bhi8K+Blo8K
#define OAHI 0
#define OALO 16384
#define OBHI 32768
#define OBLO 40960
#define SMEM_OP (2 * OSTAGE)   // 98304

// ----------------- device scratch -----------------
__device__ __nv_bfloat16 g_Ws_hi[G4 * EDIM];
__device__ __nv_bfloat16 g_Ws_lo[G4 * EDIM];
__device__ __nv_bfloat16 g_Wh_hi[G4 * EDIM];
__device__ __nv_bfloat16 g_Wh_lo[G4 * EDIM];
__device__ float         g_bsum_p[G4];
// h sequence in split bf16: slot 0 = initial h, slot t+1 = h after step t
__device__ __nv_bfloat16 g_hseq_hi[(MAXT + 1) * HSZ];
__device__ __nv_bfloat16 g_hseq_lo[(MAXT + 1) * HSZ];
__device__ float         g_c[HSZ];
__device__ __nv_bfloat16 g_Wo_hi[ONB * EDIM];   // rows 34..63 remain zero (static init)
__device__ __nv_bfloat16 g_Wo_lo[ONB * EDIM];
__device__ unsigned int  g_bar;                 // grid barrier (reset each launch)

// ----------------- helpers -----------------
__device__ __forceinline__ uint32_t smem_u32(const void* p) {
    uint32_t a;
    asm("{ .reg .u64 t; cvta.to.shared.u64 t, %1; cvt.u32.u64 %0, t; }" : "=r"(a) : "l"(p));
    return a;
}
__device__ __forceinline__ void cpa16(uint32_t dst, const void* src) {
    asm volatile("cp.async.cg.shared.global [%0], [%1], 16;" :: "r"(dst), "l"(src));
}
__device__ __forceinline__ void cpa_commit() {
    asm volatile("cp.async.commit_group;" ::: "memory");
}
__device__ __forceinline__ void ldsm4(uint32_t* r, uint32_t a) {
    asm volatile("ldmatrix.sync.aligned.m8n8.x4.shared.b16 {%0,%1,%2,%3}, [%4];"
                 : "=r"(r[0]), "=r"(r[1]), "=r"(r[2]), "=r"(r[3]) : "r"(a));
}
__device__ __forceinline__ void mma16816(float* d,
                                         const uint32_t* a,
                                         uint32_t b0, uint32_t b1) {
    asm volatile("mma.sync.aligned.m16n8k16.row.col.f32.bf16.bf16.f32 "
                 "{%0,%1,%2,%3}, {%4,%5,%6,%7}, {%8,%9}, {%0,%1,%2,%3};"
                 : "+f"(d[0]), "+f"(d[1]), "+f"(d[2]), "+f"(d[3])
                 : "r"(a[0]), "r"(a[1]), "r"(a[2]), "r"(a[3]), "r"(b0), "r"(b1));
}
__device__ __forceinline__ float fsig(float x) {
    float t = __expf(-x);
    return __fdividef(1.f, 1.f + t);
}
__device__ __forceinline__ float ftanh_(float x) {
    float t = __expf(-2.f * x);
    return __fdividef(1.f - t, 1.f + t);
}
__device__ __forceinline__ void bsplit(float v, unsigned short& h, unsigned short& l) {
    __nv_bfloat16 hb = __float2bfloat16(v);
    float r = v - __bfloat162float(hb);
    __nv_bfloat16 lb = __float2bfloat16(r);
    h = __bfloat16_as_ushort(hb);
    l = __bfloat16_as_ushort(lb);
}

// permutation: original W row r = g*1024 + e  ->  rp = (e>>6)*256 + g*64 + (e&63)

// ----------------- prep kernels -----------------
__global__ void prep_w(const float* __restrict__ Wih, const float* __restrict__ Whh) {
    int id = blockIdx.x * 256 + threadIdx.x;
    int r = id >> 8;
    int q = id & 255;
    float4 a = reinterpret_cast<const float4*>(Wih)[(size_t)r * 256 + q];
    float4 b = reinterpret_cast<const float4*>(Whh)[(size_t)r * 256 + q];
    int g = r >> 10, e = r & 1023;
    int rp = ((e >> 6) << 8) + (g << 6) + (e & 63);
    size_t o = (size_t)rp * 256 + q;

    ushort4 hh, hl, sh, sl;
    bsplit(b.x, hh.x, hl.x); bsplit(b.y, hh.y, hl.y);
    bsplit(b.z, hh.z, hl.z); bsplit(b.w, hh.w, hl.w);
    float4 s = make_float4(a.x + b.x, a.y + b.y, a.z + b.z, a.w + b.w);
    bsplit(s.x, sh.x, sl.x); bsplit(s.y, sh.y, sl.y);
    bsplit(s.z, sh.z, sl.z); bsplit(s.w, sh.w, sl.w);

    reinterpret_cast<ushort4*>(g_Wh_hi)[o] = hh;
    reinterpret_cast<ushort4*>(g_Wh_lo)[o] = hl;
    reinterpret_cast<ushort4*>(g_Ws_hi)[o] = sh;
    reinterpret_cast<ushort4*>(g_Ws_lo)[o] = sl;
}

__global__ void prep_state(const float* __restrict__ h0, const float* __restrict__ c0,
                           const float* __restrict__ bih, const float* __restrict__ bhh,
                           const float* __restrict__ Wo) {
    int id = blockIdx.x * 256 + threadIdx.x;
    if (id == 0) g_bar = 0u;
    float4 hv = reinterpret_cast<const float4*>(h0)[id];
    ushort4 hh, hl;
    bsplit(hv.x, hh.x, hl.x); bsplit(hv.y, hh.y, hl.y);
    bsplit(hv.z, hh.z, hl.z); bsplit(hv.w, hh.w, hl.w);
    reinterpret_cast<ushort4*>(g_hseq_hi)[id] = hh;   // slot 0
    reinterpret_cast<ushort4*>(g_hseq_lo)[id] = hl;
    reinterpret_cast<float4*>(g_c)[id] = reinterpret_cast<const float4*>(c0)[id];
    if (id < G4) {
        int g = id >> 10, e = id & 1023;
        int rp = ((e >> 6) << 8) + (g << 6) + (e & 63);
        g_bsum_p[rp] = bih[id] + bhh[id];
    }
    if (id < OUTD * 256) {        // W_out split: 34 rows x 256 float4
        int r = id >> 8, q = id & 255;
        float4 wv = reinterpret_cast<const float4*>(Wo)[(size_t)r * 256 + q];
        ushort4 wh, wl;
        bsplit(wv.x, wh.x, wl.x); bsplit(wv.y, wh.y, wl.y);
        bsplit(wv.z, wh.z, wl.z); bsplit(wv.w, wh.w, wl.w);
        reinterpret_cast<ushort4*>(g_Wo_hi)[(size_t)r * 256 + q] = wh;
        reinterpret_cast<ushort4*>(g_Wo_lo)[(size_t)r * 256 + q] = wl;
    }
}

// ----------------- persistent fused GEMM + LSTM (all T steps, grid barrier) ---
__global__ __launch_bounds__(NTHREADS, 1)
void lstm_persist(int T) {
    extern __shared__ char smem[];
    float* bias_sm = reinterpret_cast<float*>(smem);
    const uint32_t sbase = smem_u32(smem) + 1024;
    const int tid = threadIdx.x;
    const int lane = tid & 31;
    const int w = tid >> 5;
    const int wm = w & 3;
    const int we = w >> 2;
    const int nb = blockIdx.x;
    const int mb = blockIdx.y;
    const int m0 = mb * BM, n0 = nb * BN;

    if (tid < BN) bias_sm[tid] = g_bsum_p[n0 + tid];
    __syncthreads();

    const int lrow = tid >> 3;
    const int lq = tid & 7;
    const int arl = (lane & 7) + ((lane >> 3) & 1) * 8;
    const int adq = lane >> 4;
    const int bn = (lane & 7) + ((lane >> 4) << 3);
    const int bdq = (lane >> 3) & 1;
    const int mbase = m0 + wm * 32 + (lane >> 2);
    const int cp2 = (lane & 3) * 2;

#define LOAD_STAGE(s, kc)                                                          \
    {                                                                              \
        uint32_t sb = sbase + (s) * STAGEB;                                        \
        size_t gc = (size_t)(kc) * 64 + lq * 8;                                    \
        _Pragma("unroll")                                                          \
        for (int i = 0; i < 2; ++i) {                                              \
            int row = lrow + i * 64;                                               \
            uint32_t sf = (uint32_t)row * 128 + (((lq ^ (row & 7)) << 4));         \
            cpa16(sb + AHI + sf, hin_hi + (size_t)(m0 + row) * EDIM + gc);         \
            cpa16(sb + ALO + sf, hin_lo + (size_t)(m0 + row) * EDIM + gc);         \
        }                                                                          \
        _Pragma("unroll")                                                          \
        for (int i = 0; i < 4; ++i) {                                              \
            int row = lrow + i * 64;                                               \
            uint32_t sf = (uint32_t)row * 128 + (((lq ^ (row & 7)) << 4));         \
            cpa16(sb + BHI + sf, Bh + (size_t)(n0 + row) * EDIM + gc);             \
            cpa16(sb + BLO + sf, Bl + (size_t)(n0 + row) * EDIM + gc);             \
        }                                                                          \
        cpa_commit();                                                              \
    }

    for (int t = 0; t < T; ++t) {
        const __nv_bfloat16* hin_hi = g_hseq_hi + (size_t)t * HSZ;
        const __nv_bfloat16* hin_lo = g_hseq_lo + (size_t)t * HSZ;
        __nv_bfloat16* hout_hi = g_hseq_hi + (size_t)(t + 1) * HSZ;
        __nv_bfloat16* hout_lo = g_hseq_lo + (size_t)(t + 1) * HSZ;
        const __nv_bfloat16* Bh = t ? g_Ws_hi : g_Wh_hi;
        const __nv_bfloat16* Bl = t ? g_Ws_lo : g_Wh_lo;

        float acc[2][4][2][4];
#pragma unroll
        for (int i = 0; i < 2; ++i)
#pragma unroll
            for (int j = 0; j < 4; ++j)
#pragma unroll
                for (int s = 0; s < 2; ++s)
#pragma unroll
                    for (int k = 0; k < 4; ++k) acc[i][j][s][k] = 0.f;

        LOAD_STAGE(0, 0)

        for (int kc = 0; kc < NCK; ++kc) {
            asm volatile("cp.async.wait_group 0;" ::: "memory");
            __syncthreads();
            if (kc + 1 < NCK) {
                LOAD_STAGE((kc + 1) & 1, kc + 1)
            }
            uint32_t sb = sbase + (kc & 1) * STAGEB;
#pragma unroll
            for (int k16 = 0; k16 < 4; ++k16) {
                int qa = k16 * 2 + adq;
                int qb = k16 * 2 + bdq;
                uint32_t aoffs[2], boffs[4];
#pragma unroll
                for (int mt = 0; mt < 2; ++mt) {
                    int ar = wm * 32 + mt * 16 + arl;
                    aoffs[mt] = (uint32_t)ar * 128 + ((qa ^ (ar & 7)) << 4);
                }
#pragma unroll
                for (int g = 0; g < 4; ++g) {
                    int br = g * 64 + we * 16 + bn;
                    boffs[g] = (uint32_t)br * 128 + ((qb ^ (br & 7)) << 4);
                }
                uint32_t ah[2][4], bf[4][4];
#pragma unroll
                for (int mt = 0; mt < 2; ++mt) ldsm4(ah[mt], sb + AHI + aoffs[mt]);
#pragma unroll
                for (int g = 0; g < 4; ++g) ldsm4(bf[g], sb + BHI + boffs[g]);
#pragma unroll
                for (int mt = 0; mt < 2; ++mt)
#pragma unroll
                    for (int g = 0; g < 4; ++g) {
                        mma16816(acc[mt][g][0], ah[mt], bf[g][0], bf[g][1]);
                        mma16816(acc[mt][g][1], ah[mt], bf[g][2], bf[g][3]);
                    }
                {
                    uint32_t al[2][4];
#pragma unroll
                    for (int mt = 0; mt < 2; ++mt) ldsm4(al[mt], sb + ALO + aoffs[mt]);
#pragma unroll
                    for (int mt = 0; mt < 2; ++mt)
#pragma unroll
                        for (int g = 0; g < 4; ++g) {
                            mma16816(acc[mt][g][0], al[mt], bf[g][0], bf[g][1]);
                            mma16816(acc[mt][g][1], al[mt], bf[g][2], bf[g][3]);
                        }
                }
#pragma unroll
                for (int g = 0; g < 4; ++g) ldsm4(bf[g], sb + BLO + boffs[g]);
#pragma unroll
                for (int mt = 0; mt < 2; ++mt)
#pragma unroll
                    for (int g = 0; g < 4; ++g) {
                        mma16816(acc[mt][g][0], ah[mt], bf[g][0], bf[g][1]);
                        mma16816(acc[mt][g][1], ah[mt], bf[g][2], bf[g][3]);
                    }
            }
        }

        // ---- fused epilogue ----
#pragma unroll
        for (int mt = 0; mt < 2; ++mt) {
#pragma unroll
            for (int rr = 0; rr < 2; ++rr) {
                int m = mbase + mt * 16 + rr * 8;
#pragma unroll
                for (int sub = 0; sub < 2; ++sub) {
                    int el = we * 16 + sub * 8 + cp2;
                    float xi0 = acc[mt][0][sub][rr*2+0] + bias_sm[el];
                    float xi1 = acc[mt][0][sub][rr*2+1] + bias_sm[el + 1];
                    float xf0 = acc[mt][1][sub][rr*2+0] + bias_sm[64 + el];
                    float xf1 = acc[mt][1][sub][rr*2+1] + bias_sm[64 + el + 1];
                    float xg0 = acc[mt][2][sub][rr*2+0] + bias_sm[128 + el];
                    float xg1 = acc[mt][2][sub][rr*2+1] + bias_sm[128 + el + 1];
                    float xo0 = acc[mt][3][sub][rr*2+0] + bias_sm[192 + el];
                    float xo1 = acc[mt][3][sub][rr*2+1] + bias_sm[192 + el + 1];
                    size_t off = (size_t)m * EDIM + nb * 64 + el;
                    float2 cold = *reinterpret_cast<const float2*>(g_c + off);
                    float cn0 = fsig(xf0) * cold.x + fsig(xi0) * ftanh_(xg0);
                    float cn1 = fsig(xf1) * cold.y + fsig(xi1) * ftanh_(xg1);
                    float hn0 = fsig(xo0) * ftanh_(cn0);
                    float hn1 = fsig(xo1) * ftanh_(cn1);
                    *reinterpret_cast<float2*>(g_c + off) = make_float2(cn0, cn1);
                    unsigned short h0, l0, h1, l1;
                    bsplit(hn0, h0, l0);
                    bsplit(hn1, h1, l1);
                    *reinterpret_cast<uint32_t*>(reinterpret_cast<unsigned short*>(hout_hi) + off) =
                        (uint32_t)h0 | ((uint32_t)h1 << 16);
                    *reinterpret_cast<uint32_t*>(reinterpret_cast<unsigned short*>(hout_lo) + off) =
                        (uint32_t)l0 | ((uint32_t)l1 << 16);
                }
            }
        }

        if (t + 1 < T) {
            __threadfence();
            __syncthreads();
            if (tid == 0) {
                unsigned tgt = (unsigned)(t + 1) * (unsigned)NCTAS;
                atomicAdd(&g_bar, 1u);
                while (atomicAdd(&g_bar, 0u) < tgt) __nanosleep(64);
            }
            __syncthreads();
        }
    }
#undef LOAD_STAGE
}

// ----------------- output projection: bf16 3-pass tensor-core GEMM -----------
// out[(b*T + t)*34 + o] = hseq[t+1][b][:]·Wo[o][:] + bo[o]
__global__ __launch_bounds__(256, 1)
void out_proj_mma(const float* __restrict__ bo, float* __restrict__ out, int T) {
    extern __shared__ char smem[];
    const uint32_t sbase = smem_u32(smem);
    const int tid = threadIdx.x;
    const int lane = tid & 31;
    const int w = tid >> 5;        // 0..7
    const int wm = w & 3;          // m32 group
    const int wn = w >> 2;         // n32 group (0..1)
    const int gr0 = blockIdx.x * 128;      // global row base (t*1024 + b)
    const int t = gr0 >> 10;
    const int b0 = gr0 & 1023;

    const __nv_bfloat16* Ah = g_hseq_hi + (size_t)(t + 1) * HSZ + (size_t)b0 * EDIM;
    const __nv_bfloat16* Al = g_hseq_lo + (size_t)(t + 1) * HSZ + (size_t)b0 * EDIM;

    const int lrow = tid >> 3;     // 0..31
    const int lq = tid & 7;

#define OLOAD(s, kc)                                                               \
    {                                                                              \
        uint32_t sb = sbase + (s) * OSTAGE;                                        \
        size_t gc = (size_t)(kc) * 64 + lq * 8;                                    \
        _Pragma("unroll")                                                          \
        for (int i = 0; i < 4; ++i) {                                              \
            int row = lrow + i * 32;                                               \
            uint32_t sf = (uint32_t)row * 128 + (((lq ^ (row & 7)) << 4));         \
            cpa16(sb + OAHI + sf, Ah + (size_t)row * EDIM + gc);                   \
            cpa16(sb + OALO + sf, Al + (size_t)row * EDIM + gc);                   \
        }                                                                          \
        _Pragma("unroll")                                                          \
        for (int i = 0; i < 2; ++i) {                                              \
            int row = lrow + i * 32;                                               \
            uint32_t sf = (uint32_t)row * 128 + (((lq ^ (row & 7)) << 4));         \
            cpa16(sb + OBHI + sf, g_Wo_hi + (size_t)row * EDIM + gc);              \
            cpa16(sb + OBLO + sf, g_Wo_lo + (size_t)row * EDIM + gc);              \
        }                                                                          \
        cpa_commit();                                                              \
    }

    float acc[2][2][2][4];   // [mt][nt][sub][4]
#pragma unroll
    for (int i = 0; i < 2; ++i)
#pragma unroll
        for (int j = 0; j < 2; ++j)
#pragma unroll
            for (int s = 0; s < 2; ++s)
#pragma unroll
                for (int k = 0; k < 4; ++k) acc[i][j][s][k] = 0.f;

    const int arl = (lane & 7) + ((lane >> 3) & 1) * 8;
    const int adq = lane >> 4;
    const int bn = (lane & 7) + ((lane >> 4) << 3);
    const int bdq = (lane >> 3) & 1;

    OLOAD(0, 0)

    for (int kc = 0; kc < NCK; ++kc) {
        asm volatile("cp.async.wait_group 0;" ::: "memory");
        __syncthreads();
        if (kc + 1 < NCK) {
            OLOAD((kc + 1) & 1, kc + 1)
        }
        uint32_t sb = sbase + (kc & 1) * OSTAGE;
#pragma unroll
        for (int k16 = 0; k16 < 4; ++k16) {
            int qa = k16 * 2 + adq;
            int qb = k16 * 2 + bdq;
            uint32_t aoffs[2], boffs[2];
#pragma unroll
            for (int mt = 0; mt < 2; ++mt) {
                int ar = wm * 32 + mt * 16 + arl;
                aoffs[mt] = (uint32_t)ar * 128 + ((qa ^ (ar & 7)) << 4);
            }
#pragma unroll
            for (int nt = 0; nt < 2; ++nt) {
                int br = wn * 32 + nt * 16 + bn;
                boffs[nt] = (uint32_t)br * 128 + ((qb ^ (br & 7)) << 4);
            }
            uint32_t ah[2][4], bf[2][4];
#pragma unroll
            for (int mt = 0; mt < 2; ++mt) ldsm4(ah[mt], sb + OAHI + aoffs[mt]);
#pragma unroll
            for (int nt = 0; nt < 2; ++nt) ldsm4(bf[nt], sb + OBHI + boffs[nt]);
#pragma unroll
            for (int mt = 0; mt < 2; ++mt)
#pragma unroll
                for (int nt = 0; nt < 2; ++nt) {
                    mma16816(acc[mt][nt][0], ah[mt], bf[nt][0], bf[nt][1]);
                    mma16816(acc[mt][nt][1], ah[mt], bf[nt][2], bf[nt][3]);
                }
            {
                uint32_t al[2][4];
#pragma unroll
                for (int mt = 0; mt < 2; ++mt) ldsm4(al[mt], sb + OALO + aoffs[mt]);
#pragma unroll
                for (int mt = 0; mt < 2; ++mt)
#pragma unroll
                    for (int nt = 0; nt < 2; ++nt) {
                        mma16816(acc[mt][nt][0], al[mt], bf[nt][0], bf[nt][1]);
                        mma16816(acc[mt][nt][1], al[mt], bf[nt][2], bf[nt][3]);
                    }
            }
#pragma unroll
            for (int nt = 0; nt < 2; ++nt) ldsm4(bf[nt], sb + OBLO + boffs[nt]);
#pragma unroll
            for (int mt = 0; mt < 2; ++mt)
#pragma unroll
                for (int nt = 0; nt < 2; ++nt) {
                    mma16816(acc[mt][nt][0], ah[mt], bf[nt][0], bf[nt][1]);
                    mma16816(acc[mt][nt][1], ah[mt], bf[nt][2], bf[nt][3]);
                }
        }
    }
#undef OLOAD

    // epilogue: bias + scattered store (only o < 34)
    const int rbase = wm * 32 + (lane >> 2);
    const int cp2 = (lane & 3) * 2;
#pragma unroll
    for (int mt = 0; mt < 2; ++mt) {
#pragma unroll
        for (int rr = 0; rr < 2; ++rr) {
            int b = b0 + rbase + mt * 16 + rr * 8;
            size_t ob = ((size_t)b * T + t) * OUTD;
#pragma unroll
            for (int nt = 0; nt < 2; ++nt) {
#pragma unroll
                for (int sub = 0; sub < 2; ++sub) {
                    int o = wn * 32 + nt * 16 + sub * 8 + cp2;
                    if (o < OUTD)
                        out[ob + o] = acc[mt][nt][sub][rr*2+0] + __ldg(bo + o);
                    if (o + 1 < OUTD)
                        out[ob + o + 1] = acc[mt][nt][sub][rr*2+1] + __ldg(bo + o + 1);
                }
            }
        }
    }
}

// ----------------- launch -----------------
extern "C" void kernel_launch(void* const* d_in, const int* in_sizes, int n_in,
                              void* d_out, int out_size) {
    const float* h     = (const float*)d_in[0];
    const float* c     = (const float*)d_in[1];
    const float* W_ih  = (const float*)d_in[2];
    const float* W_hh  = (const float*)d_in[3];
    const float* b_ih  = (const float*)d_in[4];
    const float* b_hh  = (const float*)d_in[5];
    const float* W_out = (const float*)d_in[6];
    const float* b_out = (const float*)d_in[7];
    float* out = (float*)d_out;

    int T = out_size / (BDIM * OUTD);
    if (T < 1) T = 1;
    if (T > MAXT) T = MAXT;

    cudaFuncSetAttribute(lstm_persist, cudaFuncAttributeMaxDynamicSharedMemorySize, SMEM_LSTM);
    cudaFuncSetAttribute(out_proj_mma, cudaFuncAttributeMaxDynamicSharedMemorySize, SMEM_OP);

    prep_w<<<G4, 256>>>(W_ih, W_hh);
    prep_state<<<(BDIM * EDIM / 4) / 256, 256>>>(h, c, b_ih, b_hh, W_out);

    dim3 grid(G4 / BN, BDIM / BM);   // (16, 8) = 128 CTAs = 1 per SM, all resident
    lstm_persist<<<grid, NTHREADS, SMEM_LSTM>>>(T);

    out_proj_mma<<<8 * T, 256, SMEM_OP>>>(b_out, out, T);
}

// round 14
// speedup vs baseline: 1.9370x; 1.4127x over previous
#include <cuda_runtime.h>
#include <cuda_fp16.h>
#include <cstdint>

#define EDIM 1024
#define BDIM 1024
#define G4   4096
#define MAXT 16
#define OUTD 34

#define BM 128
#define BN 256
#define BK 64
#define NCK (EDIM / BK)        // 16 k-chunks
#define NTHREADS 512
#define NCTAS 128

#define STAGEB 65536           // Ahi16K + Alo16K + Bhi32K
#define AHI 0
#define ALO 16384
#define BHI 32768
#define SMEM_LSTM (1024 + 2 * STAGEB)   // bias + 2 stages = 132096

#define HSZ (BDIM * EDIM)

// out_proj GEMM tiling
#define ONB 64
#define OSTAGE 40960           // Ahi16K + Alo16K + Bhi8K
#define OAHI 0
#define OALO 16384
#define OBHI 32768
#define SMEM_OP (2 * OSTAGE)   // 81920

// ----------------- device scratch -----------------
__device__ __half g_Ws_h[G4 * EDIM];      // fp16(Wih+Whh), permuted
__device__ __half g_Wh_h[G4 * EDIM];      // fp16(Whh), permuted (step 0)
__device__ float  g_bsum_p[G4];
// h sequence in split fp16: slot 0 = initial h, slot t+1 = h after step t
__device__ __half g_hseq_hi[(MAXT + 1) * HSZ];
__device__ __half g_hseq_lo[(MAXT + 1) * HSZ];
__device__ float  g_c[HSZ];
__device__ __half g_Wo_h[ONB * EDIM];     // rows 34..63 stay zero
__device__ unsigned int g_bar;            // grid barrier (reset each launch)

// ----------------- helpers -----------------
__device__ __forceinline__ uint32_t smem_u32(const void* p) {
    uint32_t a;
    asm("{ .reg .u64 t; cvta.to.shared.u64 t, %1; cvt.u32.u64 %0, t; }" : "=r"(a) : "l"(p));
    return a;
}
__device__ __forceinline__ void cpa16(uint32_t dst, const void* src) {
    asm volatile("cp.async.cg.shared.global [%0], [%1], 16;" :: "r"(dst), "l"(src));
}
__device__ __forceinline__ void cpa_commit() {
    asm volatile("cp.async.commit_group;" ::: "memory");
}
__device__ __forceinline__ void ldsm4(uint32_t* r, uint32_t a) {
    asm volatile("ldmatrix.sync.aligned.m8n8.x4.shared.b16 {%0,%1,%2,%3}, [%4];"
                 : "=r"(r[0]), "=r"(r[1]), "=r"(r[2]), "=r"(r[3]) : "r"(a));
}
__device__ __forceinline__ void mma16816(float* d,
                                         const uint32_t* a,
                                         uint32_t b0, uint32_t b1) {
    asm volatile("mma.sync.aligned.m16n8k16.row.col.f32.f16.f16.f32 "
                 "{%0,%1,%2,%3}, {%4,%5,%6,%7}, {%8,%9}, {%0,%1,%2,%3};"
                 : "+f"(d[0]), "+f"(d[1]), "+f"(d[2]), "+f"(d[3])
                 : "r"(a[0]), "r"(a[1]), "r"(a[2]), "r"(a[3]), "r"(b0), "r"(b1));
}
__device__ __forceinline__ float fsig(float x) {
    float t = __expf(-x);
    return __fdividef(1.f, 1.f + t);
}
__device__ __forceinline__ float ftanh_(float x) {
    float t = __expf(-2.f * x);
    return __fdividef(1.f - t, 1.f + t);
}
// fp16 split: v = hi + lo with |lo| <= 2^-11 |v|
__device__ __forceinline__ void hsplit(float v, unsigned short& h, unsigned short& l) {
    __half hb = __float2half_rn(v);
    float r = v - __half2float(hb);
    h = __half_as_ushort(hb);
    l = __half_as_ushort(__float2half_rn(r));
}

// permutation: original W row r = g*1024 + e  ->  rp = (e>>6)*256 + g*64 + (e&63)

// ----------------- prep kernels -----------------
__global__ void prep_w(const float* __restrict__ Wih, const float* __restrict__ Whh) {
    int id = blockIdx.x * 256 + threadIdx.x;
    int r = id >> 8;
    int q = id & 255;
    float4 a = reinterpret_cast<const float4*>(Wih)[(size_t)r * 256 + q];
    float4 b = reinterpret_cast<const float4*>(Whh)[(size_t)r * 256 + q];
    int g = r >> 10, e = r & 1023;
    int rp = ((e >> 6) << 8) + (g << 6) + (e & 63);
    size_t o = (size_t)rp * 256 + q;

    ushort4 wh, ws;
    wh.x = __half_as_ushort(__float2half_rn(b.x));
    wh.y = __half_as_ushort(__float2half_rn(b.y));
    wh.z = __half_as_ushort(__float2half_rn(b.z));
    wh.w = __half_as_ushort(__float2half_rn(b.w));
    ws.x = __half_as_ushort(__float2half_rn(a.x + b.x));
    ws.y = __half_as_ushort(__float2half_rn(a.y + b.y));
    ws.z = __half_as_ushort(__float2half_rn(a.z + b.z));
    ws.w = __half_as_ushort(__float2half_rn(a.w + b.w));

    reinterpret_cast<ushort4*>(g_Wh_h)[o] = wh;
    reinterpret_cast<ushort4*>(g_Ws_h)[o] = ws;
}

__global__ void prep_state(const float* __restrict__ h0, const float* __restrict__ c0,
                           const float* __restrict__ bih, const float* __restrict__ bhh,
                           const float* __restrict__ Wo) {
    int id = blockIdx.x * 256 + threadIdx.x;
    if (id == 0) g_bar = 0u;
    float4 hv = reinterpret_cast<const float4*>(h0)[id];
    ushort4 hh, hl;
    hsplit(hv.x, hh.x, hl.x); hsplit(hv.y, hh.y, hl.y);
    hsplit(hv.z, hh.z, hl.z); hsplit(hv.w, hh.w, hl.w);
    reinterpret_cast<ushort4*>(g_hseq_hi)[id] = hh;   // slot 0
    reinterpret_cast<ushort4*>(g_hseq_lo)[id] = hl;
    reinterpret_cast<float4*>(g_c)[id] = reinterpret_cast<const float4*>(c0)[id];
    if (id < G4) {
        int g = id >> 10, e = id & 1023;
        int rp = ((e >> 6) << 8) + (g << 6) + (e & 63);
        g_bsum_p[rp] = bih[id] + bhh[id];
    }
    if (id < OUTD * 256) {        // W_out: 34 rows x 256 float4 -> fp16
        int r = id >> 8, q = id & 255;
        float4 wv = reinterpret_cast<const float4*>(Wo)[(size_t)r * 256 + q];
        ushort4 wh;
        wh.x = __half_as_ushort(__float2half_rn(wv.x));
        wh.y = __half_as_ushort(__float2half_rn(wv.y));
        wh.z = __half_as_ushort(__float2half_rn(wv.z));
        wh.w = __half_as_ushort(__float2half_rn(wv.w));
        reinterpret_cast<ushort4*>(g_Wo_h)[(size_t)r * 256 + q] = wh;
    }
}

// ----------------- persistent fused GEMM + LSTM (all T steps, grid barrier) ---
__global__ __launch_bounds__(NTHREADS, 1)
void lstm_persist(int T) {
    extern __shared__ char smem[];
    float* bias_sm = reinterpret_cast<float*>(smem);
    const uint32_t sbase = smem_u32(smem) + 1024;
    const int tid = threadIdx.x;
    const int lane = tid & 31;
    const int w = tid >> 5;
    const int wm = w & 3;
    const int we = w >> 2;
    const int nb = blockIdx.x;
    const int mb = blockIdx.y;
    const int m0 = mb * BM, n0 = nb * BN;

    if (tid < BN) bias_sm[tid] = g_bsum_p[n0 + tid];
    __syncthreads();

    const int lrow = tid >> 3;
    const int lq = tid & 7;
    const int arl = (lane & 7) + ((lane >> 3) & 1) * 8;
    const int adq = lane >> 4;
    const int bn = (lane & 7) + ((lane >> 4) << 3);
    const int bdq = (lane >> 3) & 1;
    const int mbase = m0 + wm * 32 + (lane >> 2);
    const int cp2 = (lane & 3) * 2;

#define LOAD_STAGE(s, kc)                                                          \
    {                                                                              \
        uint32_t sb = sbase + (s) * STAGEB;                                        \
        size_t gc = (size_t)(kc) * 64 + lq * 8;                                    \
        _Pragma("unroll")                                                          \
        for (int i = 0; i < 2; ++i) {                                              \
            int row = lrow + i * 64;                                               \
            uint32_t sf = (uint32_t)row * 128 + (((lq ^ (row & 7)) << 4));         \
            cpa16(sb + AHI + sf, hin_hi + (size_t)(m0 + row) * EDIM + gc);         \
            cpa16(sb + ALO + sf, hin_lo + (size_t)(m0 + row) * EDIM + gc);         \
        }                                                                          \
        _Pragma("unroll")                                                          \
        for (int i = 0; i < 4; ++i) {                                              \
            int row = lrow + i * 64;                                               \
            uint32_t sf = (uint32_t)row * 128 + (((lq ^ (row & 7)) << 4));         \
            cpa16(sb + BHI + sf, Bh + (size_t)(n0 + row) * EDIM + gc);             \
        }                                                                          \
        cpa_commit();                                                              \
    }

    for (int t = 0; t < T; ++t) {
        const __half* hin_hi = g_hseq_hi + (size_t)t * HSZ;
        const __half* hin_lo = g_hseq_lo + (size_t)t * HSZ;
        __half* hout_hi = g_hseq_hi + (size_t)(t + 1) * HSZ;
        __half* hout_lo = g_hseq_lo + (size_t)(t + 1) * HSZ;
        const __half* Bh = t ? g_Ws_h : g_Wh_h;

        float acc[2][4][2][4];
#pragma unroll
        for (int i = 0; i < 2; ++i)
#pragma unroll
            for (int j = 0; j < 4; ++j)
#pragma unroll
                for (int s = 0; s < 2; ++s)
#pragma unroll
                    for (int k = 0; k < 4; ++k) acc[i][j][s][k] = 0.f;

        LOAD_STAGE(0, 0)

        for (int kc = 0; kc < NCK; ++kc) {
            asm volatile("cp.async.wait_group 0;" ::: "memory");
            __syncthreads();
            if (kc + 1 < NCK) {
                LOAD_STAGE((kc + 1) & 1, kc + 1)
            }
            uint32_t sb = sbase + (kc & 1) * STAGEB;
#pragma unroll
            for (int k16 = 0; k16 < 4; ++k16) {
                int qa = k16 * 2 + adq;
                int qb = k16 * 2 + bdq;
                uint32_t aoffs[2], boffs[4];
#pragma unroll
                for (int mt = 0; mt < 2; ++mt) {
                    int ar = wm * 32 + mt * 16 + arl;
                    aoffs[mt] = (uint32_t)ar * 128 + ((qa ^ (ar & 7)) << 4);
                }
#pragma unroll
                for (int g = 0; g < 4; ++g) {
                    int br = g * 64 + we * 16 + bn;
                    boffs[g] = (uint32_t)br * 128 + ((qb ^ (br & 7)) << 4);
                }
                uint32_t ah[2][4], bf[4][4];
#pragma unroll
                for (int mt = 0; mt < 2; ++mt) ldsm4(ah[mt], sb + AHI + aoffs[mt]);
#pragma unroll
                for (int g = 0; g < 4; ++g) ldsm4(bf[g], sb + BHI + boffs[g]);
                // pass 1: h_hi * W
#pragma unroll
                for (int mt = 0; mt < 2; ++mt)
#pragma unroll
                    for (int g = 0; g < 4; ++g) {
                        mma16816(acc[mt][g][0], ah[mt], bf[g][0], bf[g][1]);
                        mma16816(acc[mt][g][1], ah[mt], bf[g][2], bf[g][3]);
                    }
                // pass 2: h_lo * W
                {
                    uint32_t al[2][4];
#pragma unroll
                    for (int mt = 0; mt < 2; ++mt) ldsm4(al[mt], sb + ALO + aoffs[mt]);
#pragma unroll
                    for (int mt = 0; mt < 2; ++mt)
#pragma unroll
                        for (int g = 0; g < 4; ++g) {
                            mma16816(acc[mt][g][0], al[mt], bf[g][0], bf[g][1]);
                            mma16816(acc[mt][g][1], al[mt], bf[g][2], bf[g][3]);
                        }
                }
            }
        }

        // ---- fused epilogue ----
#pragma unroll
        for (int mt = 0; mt < 2; ++mt) {
#pragma unroll
            for (int rr = 0; rr < 2; ++rr) {
                int m = mbase + mt * 16 + rr * 8;
#pragma unroll
                for (int sub = 0; sub < 2; ++sub) {
                    int el = we * 16 + sub * 8 + cp2;
                    float xi0 = acc[mt][0][sub][rr*2+0] + bias_sm[el];
                    float xi1 = acc[mt][0][sub][rr*2+1] + bias_sm[el + 1];
                    float xf0 = acc[mt][1][sub][rr*2+0] + bias_sm[64 + el];
                    float xf1 = acc[mt][1][sub][rr*2+1] + bias_sm[64 + el + 1];
                    float xg0 = acc[mt][2][sub][rr*2+0] + bias_sm[128 + el];
                    float xg1 = acc[mt][2][sub][rr*2+1] + bias_sm[128 + el + 1];
                    float xo0 = acc[mt][3][sub][rr*2+0] + bias_sm[192 + el];
                    float xo1 = acc[mt][3][sub][rr*2+1] + bias_sm[192 + el + 1];
                    size_t off = (size_t)m * EDIM + nb * 64 + el;
                    float2 cold = *reinterpret_cast<const float2*>(g_c + off);
                    float cn0 = fsig(xf0) * cold.x + fsig(xi0) * ftanh_(xg0);
                    float cn1 = fsig(xf1) * cold.y + fsig(xi1) * ftanh_(xg1);
                    float hn0 = fsig(xo0) * ftanh_(cn0);
                    float hn1 = fsig(xo1) * ftanh_(cn1);
                    *reinterpret_cast<float2*>(g_c + off) = make_float2(cn0, cn1);
                    unsigned short h0, l0, h1, l1;
                    hsplit(hn0, h0, l0);
                    hsplit(hn1, h1, l1);
                    *reinterpret_cast<uint32_t*>(reinterpret_cast<unsigned short*>(hout_hi) + off) =
                        (uint32_t)h0 | ((uint32_t)h1 << 16);
                    *reinterpret_cast<uint32_t*>(reinterpret_cast<unsigned short*>(hout_lo) + off) =
                        (uint32_t)l0 | ((uint32_t)l1 << 16);
                }
            }
        }

        if (t + 1 < T) {
            __threadfence();
            __syncthreads();
            if (tid == 0) {
                unsigned tgt = (unsigned)(t + 1) * (unsigned)NCTAS;
                atomicAdd(&g_bar, 1u);
                while (atomicAdd(&g_bar, 0u) < tgt) __nanosleep(64);
            }
            __syncthreads();
        }
    }
#undef LOAD_STAGE
}

// ----------------- output projection: fp16 2-pass tensor-core GEMM -----------
__global__ __launch_bounds__(256, 1)
void out_proj_mma(const float* __restrict__ bo, float* __restrict__ out, int T) {
    extern __shared__ char smem[];
    const uint32_t sbase = smem_u32(smem);
    const int tid = threadIdx.x;
    const int lane = tid & 31;
    const int w = tid >> 5;        // 0..7
    const int wm = w & 3;
    const int wn = w >> 2;         // 0..1
    const int gr0 = blockIdx.x * 128;      // t*1024 + b
    const int t = gr0 >> 10;
    const int b0 = gr0 & 1023;

    const __half* Ah = g_hseq_hi + (size_t)(t + 1) * HSZ + (size_t)b0 * EDIM;
    const __half* Al = g_hseq_lo + (size_t)(t + 1) * HSZ + (size_t)b0 * EDIM;

    const int lrow = tid >> 3;
    const int lq = tid & 7;

#define OLOAD(s, kc)                                                               \
    {                                                                              \
        uint32_t sb = sbase + (s) * OSTAGE;                                        \
        size_t gc = (size_t)(kc) * 64 + lq * 8;                                    \
        _Pragma("unroll")                                                          \
        for (int i = 0; i < 4; ++i) {                                              \
            int row = lrow + i * 32;                                               \
            uint32_t sf = (uint32_t)row * 128 + (((lq ^ (row & 7)) << 4));         \
            cpa16(sb + OAHI + sf, Ah + (size_t)row * EDIM + gc);                   \
            cpa16(sb + OALO + sf, Al + (size_t)row * EDIM + gc);                   \
        }                                                                          \
        _Pragma("unroll")                                                          \
        for (int i = 0; i < 2; ++i) {                                              \
            int row = lrow + i * 32;                                               \
            uint32_t sf = (uint32_t)row * 128 + (((lq ^ (row & 7)) << 4));         \
            cpa16(sb + OBHI + sf, g_Wo_h + (size_t)row * EDIM + gc);               \
        }                                                                          \
        cpa_commit();                                                              \
    }

    float acc[2][2][2][4];
#pragma unroll
    for (int i = 0; i < 2; ++i)
#pragma unroll
        for (int j = 0; j < 2; ++j)
#pragma unroll
            for (int s = 0; s < 2; ++s)
#pragma unroll
                for (int k = 0; k < 4; ++k) acc[i][j][s][k] = 0.f;

    const int arl = (lane & 7) + ((lane >> 3) & 1) * 8;
    const int adq = lane >> 4;
    const int bn = (lane & 7) + ((lane >> 4) << 3);
    const int bdq = (lane >> 3) & 1;

    OLOAD(0, 0)

    for (int kc = 0; kc < NCK; ++kc) {
        asm volatile("cp.async.wait_group 0;" ::: "memory");
        __syncthreads();
        if (kc + 1 < NCK) {
            OLOAD((kc + 1) & 1, kc + 1)
        }
        uint32_t sb = sbase + (kc & 1) * OSTAGE;
#pragma unroll
        for (int k16 = 0; k16 < 4; ++k16) {
            int qa = k16 * 2 + adq;
            int qb = k16 * 2 + bdq;
            uint32_t aoffs[2], boffs[2];
#pragma unroll
            for (int mt = 0; mt < 2; ++mt) {
                int ar = wm * 32 + mt * 16 + arl;
                aoffs[mt] = (uint32_t)ar * 128 + ((qa ^ (ar & 7)) << 4);
            }
#pragma unroll
            for (int nt = 0; nt < 2; ++nt) {
                int br = wn * 32 + nt * 16 + bn;
                boffs[nt] = (uint32_t)br * 128 + ((qb ^ (br & 7)) << 4);
            }
            uint32_t ah[2][4], bf[2][4];
#pragma unroll
            for (int mt = 0; mt < 2; ++mt) ldsm4(ah[mt], sb + OAHI + aoffs[mt]);
#pragma unroll
            for (int nt = 0; nt < 2; ++nt) ldsm4(bf[nt], sb + OBHI + boffs[nt]);
#pragma unroll
            for (int mt = 0; mt < 2; ++mt)
#pragma unroll
                for (int nt = 0; nt < 2; ++nt) {
                    mma16816(acc[mt][nt][0], ah[mt], bf[nt][0], bf[nt][1]);
                    mma16816(acc[mt][nt][1], ah[mt], bf[nt][2], bf[nt][3]);
                }
            {
                uint32_t al[2][4];
#pragma unroll
                for (int mt = 0; mt < 2; ++mt) ldsm4(al[mt], sb + OALO + aoffs[mt]);
#pragma unroll
                for (int mt = 0; mt < 2; ++mt)
#pragma unroll
                    for (int nt = 0; nt < 2; ++nt) {
                        mma16816(acc[mt][nt][0], al[mt], bf[nt][0], bf[nt][1]);
                        mma16816(acc[mt][nt][1], al[mt], bf[nt][2], bf[nt][3]);
                    }
            }
        }
    }
#undef OLOAD

    const int rbase = wm * 32 + (lane >> 2);
    const int cp2 = (lane & 3) * 2;
#pragma unroll
    for (int mt = 0; mt < 2; ++mt) {
#pragma unroll
        for (int rr = 0; rr < 2; ++rr) {
            int b = b0 + rbase + mt * 16 + rr * 8;
            size_t ob = ((size_t)b * T + t) * OUTD;
#pragma unroll
            for (int nt = 0; nt < 2; ++nt) {
#pragma unroll
                for (int sub = 0; sub < 2; ++sub) {
                    int o = wn * 32 + nt * 16 + sub * 8 + cp2;
                    if (o < OUTD)
                        out[ob + o] = acc[mt][nt][sub][rr*2+0] + __ldg(bo + o);
                    if (o + 1 < OUTD)
                        out[ob + o + 1] = acc[mt][nt][sub][rr*2+1] + __ldg(bo + o + 1);
                }
            }
        }
    }
}

// ----------------- launch -----------------
extern "C" void kernel_launch(void* const* d_in, const int* in_sizes, int n_in,
                              void* d_out, int out_size) {
    const float* h     = (const float*)d_in[0];
    const float* c     = (const float*)d_in[1];
    const float* W_ih  = (const float*)d_in[2];
    const float* W_hh  = (const float*)d_in[3];
    const float* b_ih  = (const float*)d_in[4];
    const float* b_hh  = (const float*)d_in[5];
    const float* W_out = (const float*)d_in[6];
    const float* b_out = (const float*)d_in[7];
    float* out = (float*)d_out;

    int T = out_size / (BDIM * OUTD);
    if (T < 1) T = 1;
    if (T > MAXT) T = MAXT;

    cudaFuncSetAttribute(lstm_persist, cudaFuncAttributeMaxDynamicSharedMemorySize, SMEM_LSTM);
    cudaFuncSetAttribute(out_proj_mma, cudaFuncAttributeMaxDynamicSharedMemorySize, SMEM_OP);

    prep_w<<<G4, 256>>>(W_ih, W_hh);
    prep_state<<<(BDIM * EDIM / 4) / 256, 256>>>(h, c, b_ih, b_hh, W_out);

    dim3 grid(G4 / BN, BDIM / BM);   // (16, 8) = 128 CTAs = 1 per SM, all resident
    lstm_persist<<<grid, NTHREADS, SMEM_LSTM>>>(T);

    out_proj_mma<<<8 * T, 256, SMEM_OP>>>(b_out, out, T);
}

// round 15
// speedup vs baseline: 3.1413x; 1.6218x over previous
#include <cuda_runtime.h>
#include <cuda_fp16.h>
#include <cstdint>

#define EDIM 1024
#define BDIM 1024
#define G4   4096
#define MAXT 16
#define OUTD 34

#define BM 128
#define BN 256
#define BK 64
#define NCK (EDIM / BK)        // 16 k-chunks
#define NTHREADS 512
#define NCTAS 128

#define STAGEB 49152           // A16K + B32K
#define AHI 0
#define BHI 16384
#define SMEM_LSTM (1024 + 2 * STAGEB)   // bias + 2 stages = 99328

#define HSZ (BDIM * EDIM)

// out_proj GEMM tiling
#define ONB 64
#define OSTAGE 24576           // A16K + B8K
#define OAHI 0
#define OBHI 16384
#define SMEM_OP (2 * OSTAGE)   // 49152

// ----------------- device scratch -----------------
__device__ __half g_Ws_h[G4 * EDIM];      // fp16(Wih+Whh), permuted
__device__ __half g_Wh_h[G4 * EDIM];      // fp16(Whh), permuted (step 0)
__device__ float  g_bsum_p[G4];
// h sequence in fp16: slot 0 = initial h, slot t+1 = h after step t
__device__ __half g_hseq[(MAXT + 1) * HSZ];
__device__ float  g_c[HSZ];
__device__ __half g_Wo_h[ONB * EDIM];     // rows 34..63 stay zero
__device__ unsigned int g_bar;            // grid barrier (reset each launch)

// ----------------- helpers -----------------
__device__ __forceinline__ uint32_t smem_u32(const void* p) {
    uint32_t a;
    asm("{ .reg .u64 t; cvta.to.shared.u64 t, %1; cvt.u32.u64 %0, t; }" : "=r"(a) : "l"(p));
    return a;
}
__device__ __forceinline__ void cpa16(uint32_t dst, const void* src) {
    asm volatile("cp.async.cg.shared.global [%0], [%1], 16;" :: "r"(dst), "l"(src));
}
__device__ __forceinline__ void cpa_commit() {
    asm volatile("cp.async.commit_group;" ::: "memory");
}
__device__ __forceinline__ void ldsm4(uint32_t* r, uint32_t a) {
    asm volatile("ldmatrix.sync.aligned.m8n8.x4.shared.b16 {%0,%1,%2,%3}, [%4];"
                 : "=r"(r[0]), "=r"(r[1]), "=r"(r[2]), "=r"(r[3]) : "r"(a));
}
__device__ __forceinline__ void mma16816(float* d,
                                         const uint32_t* a,
                                         uint32_t b0, uint32_t b1) {
    asm volatile("mma.sync.aligned.m16n8k16.row.col.f32.f16.f16.f32 "
                 "{%0,%1,%2,%3}, {%4,%5,%6,%7}, {%8,%9}, {%0,%1,%2,%3};"
                 : "+f"(d[0]), "+f"(d[1]), "+f"(d[2]), "+f"(d[3])
                 : "r"(a[0]), "r"(a[1]), "r"(a[2]), "r"(a[3]), "r"(b0), "r"(b1));
}
__device__ __forceinline__ float fsig(float x) {
    float t = __expf(-x);
    return __fdividef(1.f, 1.f + t);
}
__device__ __forceinline__ float ftanh_(float x) {
    float t = __expf(-2.f * x);
    return __fdividef(1.f - t, 1.f + t);
}

// permutation: original W row r = g*1024 + e  ->  rp = (e>>6)*256 + g*64 + (e&63)

// ----------------- prep kernels -----------------
__global__ void prep_w(const float* __restrict__ Wih, const float* __restrict__ Whh) {
    int id = blockIdx.x * 256 + threadIdx.x;
    int r = id >> 8;
    int q = id & 255;
    float4 a = reinterpret_cast<const float4*>(Wih)[(size_t)r * 256 + q];
    float4 b = reinterpret_cast<const float4*>(Whh)[(size_t)r * 256 + q];
    int g = r >> 10, e = r & 1023;
    int rp = ((e >> 6) << 8) + (g << 6) + (e & 63);
    size_t o = (size_t)rp * 256 + q;

    ushort4 wh, ws;
    wh.x = __half_as_ushort(__float2half_rn(b.x));
    wh.y = __half_as_ushort(__float2half_rn(b.y));
    wh.z = __half_as_ushort(__float2half_rn(b.z));
    wh.w = __half_as_ushort(__float2half_rn(b.w));
    ws.x = __half_as_ushort(__float2half_rn(a.x + b.x));
    ws.y = __half_as_ushort(__float2half_rn(a.y + b.y));
    ws.z = __half_as_ushort(__float2half_rn(a.z + b.z));
    ws.w = __half_as_ushort(__float2half_rn(a.w + b.w));

    reinterpret_cast<ushort4*>(g_Wh_h)[o] = wh;
    reinterpret_cast<ushort4*>(g_Ws_h)[o] = ws;
}

__global__ void prep_state(const float* __restrict__ h0, const float* __restrict__ c0,
                           const float* __restrict__ bih, const float* __restrict__ bhh,
                           const float* __restrict__ Wo) {
    int id = blockIdx.x * 256 + threadIdx.x;
    if (id == 0) g_bar = 0u;
    float4 hv = reinterpret_cast<const float4*>(h0)[id];
    ushort4 hh;
    hh.x = __half_as_ushort(__float2half_rn(hv.x));
    hh.y = __half_as_ushort(__float2half_rn(hv.y));
    hh.z = __half_as_ushort(__float2half_rn(hv.z));
    hh.w = __half_as_ushort(__float2half_rn(hv.w));
    reinterpret_cast<ushort4*>(g_hseq)[id] = hh;   // slot 0
    reinterpret_cast<float4*>(g_c)[id] = reinterpret_cast<const float4*>(c0)[id];
    if (id < G4) {
        int g = id >> 10, e = id & 1023;
        int rp = ((e >> 6) << 8) + (g << 6) + (e & 63);
        g_bsum_p[rp] = bih[id] + bhh[id];
    }
    if (id < OUTD * 256) {        // W_out: 34 rows x 256 float4 -> fp16
        int r = id >> 8, q = id & 255;
        float4 wv = reinterpret_cast<const float4*>(Wo)[(size_t)r * 256 + q];
        ushort4 wh;
        wh.x = __half_as_ushort(__float2half_rn(wv.x));
        wh.y = __half_as_ushort(__float2half_rn(wv.y));
        wh.z = __half_as_ushort(__float2half_rn(wv.z));
        wh.w = __half_as_ushort(__float2half_rn(wv.w));
        reinterpret_cast<ushort4*>(g_Wo_h)[(size_t)r * 256 + q] = wh;
    }
}

// ----------------- persistent fused GEMM + LSTM (all T steps, grid barrier) ---
__global__ __launch_bounds__(NTHREADS, 1)
void lstm_persist(int T) {
    extern __shared__ char smem[];
    float* bias_sm = reinterpret_cast<float*>(smem);
    const uint32_t sbase = smem_u32(smem) + 1024;
    const int tid = threadIdx.x;
    const int lane = tid & 31;
    const int w = tid >> 5;
    const int wm = w & 3;
    const int we = w >> 2;
    const int nb = blockIdx.x;
    const int mb = blockIdx.y;
    const int m0 = mb * BM, n0 = nb * BN;

    if (tid < BN) bias_sm[tid] = g_bsum_p[n0 + tid];
    __syncthreads();

    const int lrow = tid >> 3;
    const int lq = tid & 7;
    const int arl = (lane & 7) + ((lane >> 3) & 1) * 8;
    const int adq = lane >> 4;
    const int bn = (lane & 7) + ((lane >> 4) << 3);
    const int bdq = (lane >> 3) & 1;
    const int mbase = m0 + wm * 32 + (lane >> 2);
    const int cp2 = (lane & 3) * 2;

#define LOAD_STAGE(s, kc)                                                          \
    {                                                                              \
        uint32_t sb = sbase + (s) * STAGEB;                                        \
        size_t gc = (size_t)(kc) * 64 + lq * 8;                                    \
        _Pragma("unroll")                                                          \
        for (int i = 0; i < 2; ++i) {                                              \
            int row = lrow + i * 64;                                               \
            uint32_t sf = (uint32_t)row * 128 + (((lq ^ (row & 7)) << 4));         \
            cpa16(sb + AHI + sf, hin + (size_t)(m0 + row) * EDIM + gc);            \
        }                                                                          \
        _Pragma("unroll")                                                          \
        for (int i = 0; i < 4; ++i) {                                              \
            int row = lrow + i * 64;                                               \
            uint32_t sf = (uint32_t)row * 128 + (((lq ^ (row & 7)) << 4));         \
            cpa16(sb + BHI + sf, Bh + (size_t)(n0 + row) * EDIM + gc);             \
        }                                                                          \
        cpa_commit();                                                              \
    }

    for (int t = 0; t < T; ++t) {
        const __half* hin = g_hseq + (size_t)t * HSZ;
        __half* hout = g_hseq + (size_t)(t + 1) * HSZ;
        const __half* Bh = t ? g_Ws_h : g_Wh_h;

        float acc[2][4][2][4];
#pragma unroll
        for (int i = 0; i < 2; ++i)
#pragma unroll
            for (int j = 0; j < 4; ++j)
#pragma unroll
                for (int s = 0; s < 2; ++s)
#pragma unroll
                    for (int k = 0; k < 4; ++k) acc[i][j][s][k] = 0.f;

        LOAD_STAGE(0, 0)

        for (int kc = 0; kc < NCK; ++kc) {
            asm volatile("cp.async.wait_group 0;" ::: "memory");
            __syncthreads();
            if (kc + 1 < NCK) {
                LOAD_STAGE((kc + 1) & 1, kc + 1)
            }
            uint32_t sb = sbase + (kc & 1) * STAGEB;
#pragma unroll
            for (int k16 = 0; k16 < 4; ++k16) {
                int qa = k16 * 2 + adq;
                int qb = k16 * 2 + bdq;
                uint32_t aoffs[2], boffs[4];
#pragma unroll
                for (int mt = 0; mt < 2; ++mt) {
                    int ar = wm * 32 + mt * 16 + arl;
                    aoffs[mt] = (uint32_t)ar * 128 + ((qa ^ (ar & 7)) << 4);
                }
#pragma unroll
                for (int g = 0; g < 4; ++g) {
                    int br = g * 64 + we * 16 + bn;
                    boffs[g] = (uint32_t)br * 128 + ((qb ^ (br & 7)) << 4);
                }
                uint32_t ah[2][4], bf[4][4];
#pragma unroll
                for (int mt = 0; mt < 2; ++mt) ldsm4(ah[mt], sb + AHI + aoffs[mt]);
#pragma unroll
                for (int g = 0; g < 4; ++g) ldsm4(bf[g], sb + BHI + boffs[g]);
#pragma unroll
                for (int mt = 0; mt < 2; ++mt)
#pragma unroll
                    for (int g = 0; g < 4; ++g) {
                        mma16816(acc[mt][g][0], ah[mt], bf[g][0], bf[g][1]);
                        mma16816(acc[mt][g][1], ah[mt], bf[g][2], bf[g][3]);
                    }
            }
        }

        // ---- fused epilogue ----
#pragma unroll
        for (int mt = 0; mt < 2; ++mt) {
#pragma unroll
            for (int rr = 0; rr < 2; ++rr) {
                int m = mbase + mt * 16 + rr * 8;
#pragma unroll
                for (int sub = 0; sub < 2; ++sub) {
                    int el = we * 16 + sub * 8 + cp2;
                    float xi0 = acc[mt][0][sub][rr*2+0] + bias_sm[el];
                    float xi1 = acc[mt][0][sub][rr*2+1] + bias_sm[el + 1];
                    float xf0 = acc[mt][1][sub][rr*2+0] + bias_sm[64 + el];
                    float xf1 = acc[mt][1][sub][rr*2+1] + bias_sm[64 + el + 1];
                    float xg0 = acc[mt][2][sub][rr*2+0] + bias_sm[128 + el];
                    float xg1 = acc[mt][2][sub][rr*2+1] + bias_sm[128 + el + 1];
                    float xo0 = acc[mt][3][sub][rr*2+0] + bias_sm[192 + el];
                    float xo1 = acc[mt][3][sub][rr*2+1] + bias_sm[192 + el + 1];
                    size_t off = (size_t)m * EDIM + nb * 64 + el;
                    float2 cold = *reinterpret_cast<const float2*>(g_c + off);
                    float cn0 = fsig(xf0) * cold.x + fsig(xi0) * ftanh_(xg0);
                    float cn1 = fsig(xf1) * cold.y + fsig(xi1) * ftanh_(xg1);
                    float hn0 = fsig(xo0) * ftanh_(cn0);
                    float hn1 = fsig(xo1) * ftanh_(cn1);
                    *reinterpret_cast<float2*>(g_c + off) = make_float2(cn0, cn1);
                    uint32_t hp = (uint32_t)__half_as_ushort(__float2half_rn(hn0)) |
                                  ((uint32_t)__half_as_ushort(__float2half_rn(hn1)) << 16);
                    *reinterpret_cast<uint32_t*>(reinterpret_cast<unsigned short*>(hout) + off) = hp;
                }
            }
        }

        if (t + 1 < T) {
            __threadfence();
            __syncthreads();
            if (tid == 0) {
                unsigned tgt = (unsigned)(t + 1) * (unsigned)NCTAS;
                atomicAdd(&g_bar, 1u);
                while (atomicAdd(&g_bar, 0u) < tgt) __nanosleep(64);
            }
            __syncthreads();
        }
    }
#undef LOAD_STAGE
}

// ----------------- output projection: fp16 1-pass tensor-core GEMM -----------
__global__ __launch_bounds__(256, 1)
void out_proj_mma(const float* __restrict__ bo, float* __restrict__ out, int T) {
    extern __shared__ char smem[];
    const uint32_t sbase = smem_u32(smem);
    const int tid = threadIdx.x;
    const int lane = tid & 31;
    const int w = tid >> 5;        // 0..7
    const int wm = w & 3;
    const int wn = w >> 2;         // 0..1
    const int gr0 = blockIdx.x * 128;      // t*1024 + b
    const int t = gr0 >> 10;
    const int b0 = gr0 & 1023;

    const __half* Ah = g_hseq + (size_t)(t + 1) * HSZ + (size_t)b0 * EDIM;

    const int lrow = tid >> 3;
    const int lq = tid & 7;

#define OLOAD(s, kc)                                                               \
    {                                                                              \
        uint32_t sb = sbase + (s) * OSTAGE;                                        \
        size_t gc = (size_t)(kc) * 64 + lq * 8;                                    \
        _Pragma("unroll")                                                          \
        for (int i = 0; i < 4; ++i) {                                              \
            int row = lrow + i * 32;                                               \
            uint32_t sf = (uint32_t)row * 128 + (((lq ^ (row & 7)) << 4));         \
            cpa16(sb + OAHI + sf, Ah + (size_t)row * EDIM + gc);                   \
        }                                                                          \
        _Pragma("unroll")                                                          \
        for (int i = 0; i < 2; ++i) {                                              \
            int row = lrow + i * 32;                                               \
            uint32_t sf = (uint32_t)row * 128 + (((lq ^ (row & 7)) << 4));         \
            cpa16(sb + OBHI + sf, g_Wo_h + (size_t)row * EDIM + gc);               \
        }                                                                          \
        cpa_commit();                                                              \
    }

    float acc[2][2][2][4];
#pragma unroll
    for (int i = 0; i < 2; ++i)
#pragma unroll
        for (int j = 0; j < 2; ++j)
#pragma unroll
            for (int s = 0; s < 2; ++s)
#pragma unroll
                for (int k = 0; k < 4; ++k) acc[i][j][s][k] = 0.f;

    const int arl = (lane & 7) + ((lane >> 3) & 1) * 8;
    const int adq = lane >> 4;
    const int bn = (lane & 7) + ((lane >> 4) << 3);
    const int bdq = (lane >> 3) & 1;

    OLOAD(0, 0)

    for (int kc = 0; kc < NCK; ++kc) {
        asm volatile("cp.async.wait_group 0;" ::: "memory");
        __syncthreads();
        if (kc + 1 < NCK) {
            OLOAD((kc + 1) & 1, kc + 1)
        }
        uint32_t sb = sbase + (kc & 1) * OSTAGE;
#pragma unroll
        for (int k16 = 0; k16 < 4; ++k16) {
            int qa = k16 * 2 + adq;
            int qb = k16 * 2 + bdq;
            uint32_t aoffs[2], boffs[2];
#pragma unroll
            for (int mt = 0; mt < 2; ++mt) {
                int ar = wm * 32 + mt * 16 + arl;
                aoffs[mt] = (uint32_t)ar * 128 + ((qa ^ (ar & 7)) << 4);
            }
#pragma unroll
            for (int nt = 0; nt < 2; ++nt) {
                int br = wn * 32 + nt * 16 + bn;
                boffs[nt] = (uint32_t)br * 128 + ((qb ^ (br & 7)) << 4);
            }
            uint32_t ah[2][4], bf[2][4];
#pragma unroll
            for (int mt = 0; mt < 2; ++mt) ldsm4(ah[mt], sb + OAHI + aoffs[mt]);
#pragma unroll
            for (int nt = 0; nt < 2; ++nt) ldsm4(bf[nt], sb + OBHI + boffs[nt]);
#pragma unroll
            for (int mt = 0; mt < 2; ++mt)
#pragma unroll
                for (int nt = 0; nt < 2; ++nt) {
                    mma16816(acc[mt][nt][0], ah[mt], bf[nt][0], bf[nt][1]);
                    mma16816(acc[mt][nt][1], ah[mt], bf[nt][2], bf[nt][3]);
                }
        }
    }
#undef OLOAD

    const int rbase = wm * 32 + (lane >> 2);
    const int cp2 = (lane & 3) * 2;
#pragma unroll
    for (int mt = 0; mt < 2; ++mt) {
#pragma unroll
        for (int rr = 0; rr < 2; ++rr) {
            int b = b0 + rbase + mt * 16 + rr * 8;
            size_t ob = ((size_t)b * T + t) * OUTD;
#pragma unroll
            for (int nt = 0; nt < 2; ++nt) {
#pragma unroll
                for (int sub = 0; sub < 2; ++sub) {
                    int o = wn * 32 + nt * 16 + sub * 8 + cp2;
                    if (o < OUTD)
                        out[ob + o] = acc[mt][nt][sub][rr*2+0] + __ldg(bo + o);
                    if (o + 1 < OUTD)
                        out[ob + o + 1] = acc[mt][nt][sub][rr*2+1] + __ldg(bo + o + 1);
                }
            }
        }
    }
}

// ----------------- launch -----------------
extern "C" void kernel_launch(void* const* d_in, const int* in_sizes, int n_in,
                              void* d_out, int out_size) {
    const float* h     = (const float*)d_in[0];
    const float* c     = (const float*)d_in[1];
    const float* W_ih  = (const float*)d_in[2];
    const float* W_hh  = (const float*)d_in[3];
    const float* b_ih  = (const float*)d_in[4];
    const float* b_hh  = (const float*)d_in[5];
    const float* W_out = (const float*)d_in[6];
    const float* b_out = (const float*)d_in[7];
    float* out = (float*)d_out;

    int T = out_size / (BDIM * OUTD);
    if (T < 1) T = 1;
    if (T > MAXT) T = MAXT;

    cudaFuncSetAttribute(lstm_persist, cudaFuncAttributeMaxDynamicSharedMemorySize, SMEM_LSTM);
    cudaFuncSetAttribute(out_proj_mma, cudaFuncAttributeMaxDynamicSharedMemorySize, SMEM_OP);

    prep_w<<<G4, 256>>>(W_ih, W_hh);
    prep_state<<<(BDIM * EDIM / 4) / 256, 256>>>(h, c, b_ih, b_hh, W_out);

    dim3 grid(G4 / BN, BDIM / BM);   // (16, 8) = 128 CTAs = 1 per SM, all resident
    lstm_persist<<<grid, NTHREADS, SMEM_LSTM>>>(T);

    out_proj_mma<<<8 * T, 256, SMEM_OP>>>(b_out, out, T);
}